// round 1
// baseline (speedup 1.0000x reference)
#include <cuda_runtime.h>
#include <cstdint>

// Problem constants
#define Btok  32
#define Cdim  256
#define Hh    32
#define Ww    32
#define HW    1024            // Hh*Ww
#define Ntok  32768           // Btok*HW
#define Kcode 1024
#define Ddim  256
#define COMMIT 0.25

// Output layout (concatenated reference tuple, all fp32):
//   [0, 8388608)            out  (B,C,H,W)
//   [8388608]               loss scalar
//   [8388609]               vq_entropy scalar
//   [8388610, +33554432)    encodings (N, K) one-hot
#define OUT_ELEMS  ((size_t)Btok * Cdim * Hh * Ww)      // 8388608
#define ENC_ELEMS  ((size_t)Ntok * Kcode)               // 33554432

// ---- scratch (static device globals; no allocations allowed) ----
__device__ __align__(16) float g_wT[Ddim * Kcode];   // weight transposed [D][K], 1 MB
__device__ __align__(16) float g_wn2[Kcode];         // ||w_k||^2
__device__ int    g_idx[Ntok];                       // argmin index per token
__device__ int    g_counts[Kcode];
__device__ double g_loss;

// ---- packed f32x2 helpers (FFMA2: 2 MACs per issue slot on sm_103a) ----
#define PACK2DUP(dst, x) \
    asm("mov.b64 %0, {%1, %1};" : "=l"(dst) : "r"(__float_as_uint(x)))
#define FFMA2(c, a, b) \
    asm("fma.rn.f32x2 %0, %1, %2, %0;" : "+l"(c) : "l"(a), "l"(b))
#define UNPACK2(lo, hi, v) \
    asm("mov.b64 {%0, %1}, %2;" : "=r"(lo), "=r"(hi) : "l"(v))

// ============================================================
// zero scratch accumulators (graph replays must be idempotent)
// ============================================================
__global__ void zero_kernel() {
    int t = threadIdx.x;
    if (t < Kcode) g_counts[t] = 0;
    if (t == 0)    g_loss = 0.0;
}

// ============================================================
// transpose weight [K][D] -> g_wT [D][K]
// ============================================================
__global__ void transpose_kernel(const float* __restrict__ weight) {
    __shared__ float tile[32][33];
    int d0 = blockIdx.x * 32;   // gridDim.x = D/32 = 8
    int k0 = blockIdx.y * 32;   // gridDim.y = K/32 = 32
    int tx = threadIdx.x;       // 32
    int ty = threadIdx.y;       // 8
    #pragma unroll
    for (int j = ty; j < 32; j += 8)
        tile[j][tx] = weight[(size_t)(k0 + j) * Ddim + d0 + tx];
    __syncthreads();
    #pragma unroll
    for (int j = ty; j < 32; j += 8)
        g_wT[(size_t)(d0 + j) * Kcode + k0 + tx] = tile[tx][j];
}

// ============================================================
// per-code squared norms
// ============================================================
__global__ void wn2_kernel(const float* __restrict__ weight) {
    int k = blockIdx.x;            // 1024 blocks, 32 threads
    int lane = threadIdx.x;
    const float4* row = (const float4*)(weight + (size_t)k * Ddim);
    float s = 0.f;
    #pragma unroll
    for (int i = 0; i < 2; i++) {
        float4 v = row[lane * 2 + i];
        s += v.x * v.x + v.y * v.y + v.z * v.z + v.w * v.w;
    }
    #pragma unroll
    for (int o = 16; o > 0; o >>= 1) s += __shfl_down_sync(0xffffffffu, s, o);
    if (lane == 0) g_wn2[k] = s;
}

// ============================================================
// main: fused distance-GEMM + argmax(2 x.w - ||w||^2)
// BM=64 tokens, BN=128 codes/chunk (8 chunks), BK=8, 128 threads
// micro-tile 8 tokens x 8 codes, packed f32x2 accumulation
// ============================================================
#define BM 64
#define BN 128
#define BK 8
#define NCHUNK (Kcode / BN)   // 8
#define NTILE  (Ddim / BK)    // 32

__global__ void __launch_bounds__(128, 3)
argmin_kernel(const float* __restrict__ input) {
    const int tid = threadIdx.x;
    const int tx = tid & 15;    // code dim
    const int ty = tid >> 4;    // token dim (0..7)
    const int n0 = blockIdx.x * BM;
    const int b   = n0 / HW;
    const int rem = n0 % HW;    // 64-token block stays inside one b
    const float* aBase = input + (size_t)b * Cdim * HW + rem;

    __shared__ __align__(16) float As[2][BK][BM];
    __shared__ __align__(16) float Bs[2][BK][BN];
    __shared__ float red_v[16][BM];
    __shared__ int   red_i[16][BM];

    float bv[8];
    int   bi[8];
    #pragma unroll
    for (int i = 0; i < 8; i++) { bv[i] = -3.4e38f; bi[i] = 0; }

    const int dL = tid >> 4;          // 0..7  (load row within BK)
    const int tA = (tid & 15) * 4;    // A: token offset (float4)
    const int cL = (tid & 15) * 4;    // B: code offset  (float4)

    #pragma unroll 1
    for (int ch = 0; ch < NCHUNK; ++ch) {
        const int cb = ch * BN;

        unsigned long long acc[8][4];
        #pragma unroll
        for (int i = 0; i < 8; i++)
            #pragma unroll
            for (int j = 0; j < 4; j++) acc[i][j] = 0ull;

        // preload tile 0
        float4 pa  = *(const float4*)&aBase[(size_t)dL * HW + tA];
        float4 pb0 = *(const float4*)&g_wT[(size_t)dL * Kcode + cb + cL];
        float4 pb1 = *(const float4*)&g_wT[(size_t)dL * Kcode + cb + 64 + cL];
        *(float4*)&As[0][dL][tA]      = pa;
        *(float4*)&Bs[0][dL][cL]      = pb0;
        *(float4*)&Bs[0][dL][64 + cL] = pb1;
        __syncthreads();

        #pragma unroll 2
        for (int t = 0; t < NTILE; ++t) {
            const int buf = t & 1;
            if (t + 1 < NTILE) {
                const size_t dn = (size_t)(t + 1) * BK + dL;
                pa  = *(const float4*)&aBase[dn * HW + tA];
                pb0 = *(const float4*)&g_wT[dn * Kcode + cb + cL];
                pb1 = *(const float4*)&g_wT[dn * Kcode + cb + 64 + cL];
            }
            #pragma unroll
            for (int kk = 0; kk < BK; ++kk) {
                float4 a0 = *(const float4*)&As[buf][kk][ty * 4];
                float4 a1 = *(const float4*)&As[buf][kk][32 + ty * 4];
                ulonglong2 b0 = *(const ulonglong2*)&Bs[buf][kk][tx * 4];
                ulonglong2 b1 = *(const ulonglong2*)&Bs[buf][kk][64 + tx * 4];
                unsigned long long ad[8];
                PACK2DUP(ad[0], a0.x); PACK2DUP(ad[1], a0.y);
                PACK2DUP(ad[2], a0.z); PACK2DUP(ad[3], a0.w);
                PACK2DUP(ad[4], a1.x); PACK2DUP(ad[5], a1.y);
                PACK2DUP(ad[6], a1.z); PACK2DUP(ad[7], a1.w);
                #pragma unroll
                for (int i = 0; i < 8; i++) {
                    FFMA2(acc[i][0], ad[i], b0.x);
                    FFMA2(acc[i][1], ad[i], b0.y);
                    FFMA2(acc[i][2], ad[i], b1.x);
                    FFMA2(acc[i][3], ad[i], b1.y);
                }
            }
            if (t + 1 < NTILE) {
                const int nb = (t + 1) & 1;
                *(float4*)&As[nb][dL][tA]      = pa;
                *(float4*)&Bs[nb][dL][cL]      = pb0;
                *(float4*)&Bs[nb][dL][64 + cL] = pb1;
                __syncthreads();
            }
        }

        // chunk epilogue: score = 2*dot - ||w||^2, running argmax
        float wn[8];
        #pragma unroll
        for (int j = 0; j < 4; j++) {
            wn[j]     = g_wn2[cb + tx * 4 + j];
            wn[4 + j] = g_wn2[cb + 64 + tx * 4 + j];
        }
        #pragma unroll
        for (int i = 0; i < 8; i++) {
            #pragma unroll
            for (int jp = 0; jp < 4; jp++) {
                unsigned int ulo, uhi;
                UNPACK2(ulo, uhi, acc[i][jp]);
                float lo = __uint_as_float(ulo), hi = __uint_as_float(uhi);
                const int j0 = (jp >> 1) * 4 + (jp & 1) * 2;
                const int c0 = cb + ((jp >= 2) ? 64 : 0) + tx * 4 + (jp & 1) * 2;
                float s0 = 2.f * lo - wn[j0];
                float s1 = 2.f * hi - wn[j0 + 1];
                if (s0 > bv[i] || (s0 == bv[i] && c0 < bi[i]))     { bv[i] = s0; bi[i] = c0; }
                if (s1 > bv[i] || (s1 == bv[i] && c0 + 1 < bi[i])) { bv[i] = s1; bi[i] = c0 + 1; }
            }
        }
        __syncthreads();   // protect smem buffers before next chunk preload
    }

    // cross-thread (tx) reduction per token
    #pragma unroll
    for (int i = 0; i < 8; i++) {
        const int tl = (i < 4) ? (ty * 4 + i) : (32 + ty * 4 + (i - 4));
        red_v[tx][tl] = bv[i];
        red_i[tx][tl] = bi[i];
    }
    __syncthreads();
    if (tid < BM) {
        float v = red_v[0][tid];
        int  ix = red_i[0][tid];
        #pragma unroll
        for (int r = 1; r < 16; r++) {
            float vv = red_v[r][tid];
            int   ii = red_i[r][tid];
            if (vv > v || (vv == v && ii < ix)) { v = vv; ix = ii; }
        }
        g_idx[n0 + tid] = ix;
    }
}

// ============================================================
// writer: gather codewords -> out (BCHW) + commitment-loss partial sums
// one block = 32 tokens (same b), 256 threads
// ============================================================
__global__ void writer_kernel(const float* __restrict__ input,
                              const float* __restrict__ weight,
                              float* __restrict__ out) {
    const int tid = threadIdx.x;
    const int n0  = blockIdx.x * 32;
    const int b   = n0 / HW;
    const int hw0 = n0 % HW;

    __shared__ int   sidx[32];
    __shared__ float q[32][257];   // padded to kill bank conflicts

    if (tid < 32) sidx[tid] = g_idx[n0 + tid];
    __syncthreads();

    // coalesced gather of 32 codebook rows into smem
    for (int e4 = tid; e4 < 32 * (Ddim / 4); e4 += 256) {
        const int t  = e4 >> 6;           // token
        const int d4 = (e4 & 63) * 4;
        float4 v = *(const float4*)&weight[(size_t)sidx[t] * Ddim + d4];
        q[t][d4 + 0] = v.x; q[t][d4 + 1] = v.y;
        q[t][d4 + 2] = v.z; q[t][d4 + 3] = v.w;
    }
    __syncthreads();

    const int lane = tid & 31;
    const int cg   = tid >> 5;  // 8 channel groups
    const float* xb = input + (size_t)b * Cdim * HW;
    float*       ob = out   + (size_t)b * Cdim * HW;
    float lsum = 0.f;
    for (int c = cg; c < Cdim; c += 8) {
        const float qv = q[lane][c];
        const float xv = xb[(size_t)c * HW + hw0 + lane];
        ob[(size_t)c * HW + hw0 + lane] = qv;
        const float df = qv - xv;
        lsum += df * df;
    }

    // block reduce -> double atomic
    __shared__ float rbuf[256];
    rbuf[tid] = lsum;
    __syncthreads();
    for (int o = 128; o > 0; o >>= 1) {
        if (tid < o) rbuf[tid] += rbuf[tid + o];
        __syncthreads();
    }
    if (tid == 0) atomicAdd(&g_loss, (double)rbuf[0]);
}

// ============================================================
// one-hot encodings (buffer pre-zeroed by memset) + histogram
// ============================================================
__global__ void ones_kernel(float* __restrict__ enc) {
    const int n = blockIdx.x * blockDim.x + threadIdx.x;
    if (n < Ntok) {
        const int ix = g_idx[n];
        enc[(size_t)n * Kcode + ix] = 1.0f;
        atomicAdd(&g_counts[ix], 1);
    }
}

// ============================================================
// scalars: loss + entropy
// ============================================================
__global__ void finalize_kernel(float* __restrict__ outLoss,
                                float* __restrict__ outEnt) {
    __shared__ double sh[256];
    const int tid = threadIdx.x;
    double s = 0.0;
    for (int k = tid; k < Kcode; k += 256) {
        const float p = (float)g_counts[k] * (1.0f / (float)Ntok);
        s += (double)(p * logf(p + 1e-10f));
    }
    sh[tid] = s;
    __syncthreads();
    for (int o = 128; o > 0; o >>= 1) {
        if (tid < o) sh[tid] += sh[tid + o];
        __syncthreads();
    }
    if (tid == 0) {
        outEnt[0]  = (float)(-sh[0]);
        outLoss[0] = (float)(COMMIT * g_loss / (double)((size_t)Ntok * Ddim));
    }
}

// ============================================================
extern "C" void kernel_launch(void* const* d_in, const int* in_sizes, int n_in,
                              void* d_out, int out_size) {
    const float* input  = (const float*)d_in[0];   // [B,C,H,W] fp32
    const float* weight = (const float*)d_in[1];   // [K,D]     fp32
    float* out     = (float*)d_out;
    float* outLoss = out + OUT_ELEMS;
    float* outEnt  = outLoss + 1;
    float* enc     = outEnt + 1;

    cudaMemsetAsync(enc, 0, ENC_ELEMS * sizeof(float), 0);
    zero_kernel<<<1, 1024>>>();
    transpose_kernel<<<dim3(Ddim / 32, Kcode / 32), dim3(32, 8)>>>(weight);
    wn2_kernel<<<Kcode, 32>>>(weight);
    argmin_kernel<<<Ntok / BM, 128>>>(input);
    writer_kernel<<<Ntok / 32, 256>>>(input, weight, out);
    ones_kernel<<<Ntok / 256, 256>>>(enc);
    finalize_kernel<<<1, 256>>>(outLoss, outEnt);
}

// round 2
// speedup vs baseline: 1.0034x; 1.0034x over previous
#include <cuda_runtime.h>
#include <cstdint>

// Problem constants
#define Btok  32
#define Cdim  256
#define Hh    32
#define Ww    32
#define HW    1024            // Hh*Ww
#define Ntok  32768           // Btok*HW
#define Kcode 1024
#define Ddim  256
#define COMMIT 0.25

// Output layout (concatenated reference tuple, all fp32):
//   [0, 8388608)            out  (B,C,H,W)
//   [8388608]               loss scalar
//   [8388609]               vq_entropy scalar
//   [8388610, +33554432)    encodings (N, K) one-hot
#define OUT_ELEMS  ((size_t)Btok * Cdim * Hh * Ww)      // 8388608
#define ENC_ELEMS  ((size_t)Ntok * Kcode)               // 33554432

// ---- scratch (static device globals; no allocations allowed) ----
__device__ __align__(16) float g_wT[Ddim * Kcode];   // weight transposed [D][K], 1 MB
__device__ __align__(16) float g_wn2[Kcode];         // ||w_k||^2
__device__ int    g_idx[Ntok];                       // argmin index per token
__device__ int    g_counts[Kcode];
__device__ double g_loss;

// ---- packed f32x2 helpers (FFMA2: 2 MACs per issue slot on sm_103a) ----
#define PACK2DUP(dst, x) \
    asm("mov.b64 %0, {%1, %1};" : "=l"(dst) : "r"(__float_as_uint(x)))
#define FFMA2(c, a, b) \
    asm("fma.rn.f32x2 %0, %1, %2, %0;" : "+l"(c) : "l"(a), "l"(b))
#define UNPACK2(lo, hi, v) \
    asm("mov.b64 {%0, %1}, %2;" : "=r"(lo), "=r"(hi) : "l"(v))

// ============================================================
// zero scratch accumulators (graph replays must be idempotent)
// ============================================================
__global__ void zero_kernel() {
    int t = threadIdx.x;
    if (t < Kcode) g_counts[t] = 0;
    if (t == 0)    g_loss = 0.0;
}

// ============================================================
// transpose weight [K][D] -> g_wT [D][K]
// ============================================================
__global__ void transpose_kernel(const float* __restrict__ weight) {
    __shared__ float tile[32][33];
    int d0 = blockIdx.x * 32;   // gridDim.x = D/32 = 8
    int k0 = blockIdx.y * 32;   // gridDim.y = K/32 = 32
    int tx = threadIdx.x;       // 32
    int ty = threadIdx.y;       // 8
    #pragma unroll
    for (int j = ty; j < 32; j += 8)
        tile[j][tx] = weight[(size_t)(k0 + j) * Ddim + d0 + tx];
    __syncthreads();
    #pragma unroll
    for (int j = ty; j < 32; j += 8)
        g_wT[(size_t)(d0 + j) * Kcode + k0 + tx] = tile[tx][j];
}

// ============================================================
// per-code squared norms
// ============================================================
__global__ void wn2_kernel(const float* __restrict__ weight) {
    int k = blockIdx.x;            // 1024 blocks, 32 threads
    int lane = threadIdx.x;
    const float4* row = (const float4*)(weight + (size_t)k * Ddim);
    float s = 0.f;
    #pragma unroll
    for (int i = 0; i < 2; i++) {
        float4 v = row[lane * 2 + i];
        s += v.x * v.x + v.y * v.y + v.z * v.z + v.w * v.w;
    }
    #pragma unroll
    for (int o = 16; o > 0; o >>= 1) s += __shfl_down_sync(0xffffffffu, s, o);
    if (lane == 0) g_wn2[k] = s;
}

// ============================================================
// main: fused distance-GEMM + argmax(2 x.w - ||w||^2)
// BM=64 tokens, BN=128 codes/chunk (8 chunks), BK=8, 128 threads
// micro-tile 8 tokens x 8 codes, packed f32x2 accumulation
// ============================================================
#define BM 64
#define BN 128
#define BK 8
#define NCHUNK (Kcode / BN)   // 8
#define NTILE  (Ddim / BK)    // 32

__global__ void __launch_bounds__(128, 3)
argmin_kernel(const float* __restrict__ input) {
    const int tid = threadIdx.x;
    const int tx = tid & 15;    // code dim
    const int ty = tid >> 4;    // token dim (0..7)
    const int n0 = blockIdx.x * BM;
    const int b   = n0 / HW;
    const int rem = n0 % HW;    // 64-token block stays inside one b
    const float* aBase = input + (size_t)b * Cdim * HW + rem;

    __shared__ __align__(16) float As[2][BK][BM];
    __shared__ __align__(16) float Bs[2][BK][BN];
    __shared__ float red_v[16][BM];
    __shared__ int   red_i[16][BM];

    float bv[8];
    int   bi[8];
    #pragma unroll
    for (int i = 0; i < 8; i++) { bv[i] = -3.4e38f; bi[i] = 0; }

    const int dL = tid >> 4;          // 0..7  (load row within BK)
    const int tA = (tid & 15) * 4;    // A: token offset (float4)
    const int cL = (tid & 15) * 4;    // B: code offset  (float4)

    #pragma unroll 1
    for (int ch = 0; ch < NCHUNK; ++ch) {
        const int cb = ch * BN;

        unsigned long long acc[8][4];
        #pragma unroll
        for (int i = 0; i < 8; i++)
            #pragma unroll
            for (int j = 0; j < 4; j++) acc[i][j] = 0ull;

        // preload tile 0
        float4 pa  = *(const float4*)&aBase[(size_t)dL * HW + tA];
        float4 pb0 = *(const float4*)&g_wT[(size_t)dL * Kcode + cb + cL];
        float4 pb1 = *(const float4*)&g_wT[(size_t)dL * Kcode + cb + 64 + cL];
        *(float4*)&As[0][dL][tA]      = pa;
        *(float4*)&Bs[0][dL][cL]      = pb0;
        *(float4*)&Bs[0][dL][64 + cL] = pb1;
        __syncthreads();

        #pragma unroll 2
        for (int t = 0; t < NTILE; ++t) {
            const int buf = t & 1;
            if (t + 1 < NTILE) {
                const size_t dn = (size_t)(t + 1) * BK + dL;
                pa  = *(const float4*)&aBase[dn * HW + tA];
                pb0 = *(const float4*)&g_wT[dn * Kcode + cb + cL];
                pb1 = *(const float4*)&g_wT[dn * Kcode + cb + 64 + cL];
            }
            #pragma unroll
            for (int kk = 0; kk < BK; ++kk) {
                float4 a0 = *(const float4*)&As[buf][kk][ty * 4];
                float4 a1 = *(const float4*)&As[buf][kk][32 + ty * 4];
                ulonglong2 b0 = *(const ulonglong2*)&Bs[buf][kk][tx * 4];
                ulonglong2 b1 = *(const ulonglong2*)&Bs[buf][kk][64 + tx * 4];
                unsigned long long ad[8];
                PACK2DUP(ad[0], a0.x); PACK2DUP(ad[1], a0.y);
                PACK2DUP(ad[2], a0.z); PACK2DUP(ad[3], a0.w);
                PACK2DUP(ad[4], a1.x); PACK2DUP(ad[5], a1.y);
                PACK2DUP(ad[6], a1.z); PACK2DUP(ad[7], a1.w);
                #pragma unroll
                for (int i = 0; i < 8; i++) {
                    FFMA2(acc[i][0], ad[i], b0.x);
                    FFMA2(acc[i][1], ad[i], b0.y);
                    FFMA2(acc[i][2], ad[i], b1.x);
                    FFMA2(acc[i][3], ad[i], b1.y);
                }
            }
            if (t + 1 < NTILE) {
                const int nb = (t + 1) & 1;
                *(float4*)&As[nb][dL][tA]      = pa;
                *(float4*)&Bs[nb][dL][cL]      = pb0;
                *(float4*)&Bs[nb][dL][64 + cL] = pb1;
                __syncthreads();
            }
        }

        // chunk epilogue: score = 2*dot - ||w||^2, running argmax
        float wn[8];
        #pragma unroll
        for (int j = 0; j < 4; j++) {
            wn[j]     = g_wn2[cb + tx * 4 + j];
            wn[4 + j] = g_wn2[cb + 64 + tx * 4 + j];
        }
        #pragma unroll
        for (int i = 0; i < 8; i++) {
            #pragma unroll
            for (int jp = 0; jp < 4; jp++) {
                unsigned int ulo, uhi;
                UNPACK2(ulo, uhi, acc[i][jp]);
                float lo = __uint_as_float(ulo), hi = __uint_as_float(uhi);
                const int j0 = (jp >> 1) * 4 + (jp & 1) * 2;
                const int c0 = cb + ((jp >= 2) ? 64 : 0) + tx * 4 + (jp & 1) * 2;
                float s0 = 2.f * lo - wn[j0];
                float s1 = 2.f * hi - wn[j0 + 1];
                if (s0 > bv[i] || (s0 == bv[i] && c0 < bi[i]))     { bv[i] = s0; bi[i] = c0; }
                if (s1 > bv[i] || (s1 == bv[i] && c0 + 1 < bi[i])) { bv[i] = s1; bi[i] = c0 + 1; }
            }
        }
        __syncthreads();   // protect smem buffers before next chunk preload
    }

    // cross-thread (tx) reduction per token
    #pragma unroll
    for (int i = 0; i < 8; i++) {
        const int tl = (i < 4) ? (ty * 4 + i) : (32 + ty * 4 + (i - 4));
        red_v[tx][tl] = bv[i];
        red_i[tx][tl] = bi[i];
    }
    __syncthreads();
    if (tid < BM) {
        float v = red_v[0][tid];
        int  ix = red_i[0][tid];
        #pragma unroll
        for (int r = 1; r < 16; r++) {
            float vv = red_v[r][tid];
            int   ii = red_i[r][tid];
            if (vv > v || (vv == v && ii < ix)) { v = vv; ix = ii; }
        }
        g_idx[n0 + tid] = ix;
    }
}

// ============================================================
// writer: gather codewords -> out (BCHW) + commitment-loss partial sums
// one block = 32 tokens (same b), 256 threads
// ============================================================
__global__ void writer_kernel(const float* __restrict__ input,
                              const float* __restrict__ weight,
                              float* __restrict__ out) {
    const int tid = threadIdx.x;
    const int n0  = blockIdx.x * 32;
    const int b   = n0 / HW;
    const int hw0 = n0 % HW;

    __shared__ int   sidx[32];
    __shared__ float q[32][257];   // padded to kill bank conflicts

    if (tid < 32) sidx[tid] = g_idx[n0 + tid];
    __syncthreads();

    // coalesced gather of 32 codebook rows into smem
    for (int e4 = tid; e4 < 32 * (Ddim / 4); e4 += 256) {
        const int t  = e4 >> 6;           // token
        const int d4 = (e4 & 63) * 4;
        float4 v = *(const float4*)&weight[(size_t)sidx[t] * Ddim + d4];
        q[t][d4 + 0] = v.x; q[t][d4 + 1] = v.y;
        q[t][d4 + 2] = v.z; q[t][d4 + 3] = v.w;
    }
    __syncthreads();

    const int lane = tid & 31;
    const int cg   = tid >> 5;  // 8 channel groups
    const float* xb = input + (size_t)b * Cdim * HW;
    float*       ob = out   + (size_t)b * Cdim * HW;
    float lsum = 0.f;
    for (int c = cg; c < Cdim; c += 8) {
        const float qv = q[lane][c];
        const float xv = xb[(size_t)c * HW + hw0 + lane];
        ob[(size_t)c * HW + hw0 + lane] = qv;
        const float df = qv - xv;
        lsum += df * df;
    }

    // block reduce -> double atomic
    __shared__ float rbuf[256];
    rbuf[tid] = lsum;
    __syncthreads();
    for (int o = 128; o > 0; o >>= 1) {
        if (tid < o) rbuf[tid] += rbuf[tid + o];
        __syncthreads();
    }
    if (tid == 0) atomicAdd(&g_loss, (double)rbuf[0]);
}

// ============================================================
// one-hot encodings (buffer pre-zeroed by memset) + histogram
// ============================================================
__global__ void ones_kernel(float* __restrict__ enc) {
    const int n = blockIdx.x * blockDim.x + threadIdx.x;
    if (n < Ntok) {
        const int ix = g_idx[n];
        enc[(size_t)n * Kcode + ix] = 1.0f;
        atomicAdd(&g_counts[ix], 1);
    }
}

// ============================================================
// scalars: loss + entropy
// ============================================================
__global__ void finalize_kernel(float* __restrict__ outLoss,
                                float* __restrict__ outEnt) {
    __shared__ double sh[256];
    const int tid = threadIdx.x;
    double s = 0.0;
    for (int k = tid; k < Kcode; k += 256) {
        const float p = (float)g_counts[k] * (1.0f / (float)Ntok);
        s += (double)(p * logf(p + 1e-10f));
    }
    sh[tid] = s;
    __syncthreads();
    for (int o = 128; o > 0; o >>= 1) {
        if (tid < o) sh[tid] += sh[tid + o];
        __syncthreads();
    }
    if (tid == 0) {
        outEnt[0]  = (float)(-sh[0]);
        outLoss[0] = (float)(COMMIT * g_loss / (double)((size_t)Ntok * Ddim));
    }
}

// ============================================================
extern "C" void kernel_launch(void* const* d_in, const int* in_sizes, int n_in,
                              void* d_out, int out_size) {
    const float* input  = (const float*)d_in[0];   // [B,C,H,W] fp32
    const float* weight = (const float*)d_in[1];   // [K,D]     fp32
    float* out     = (float*)d_out;
    float* outLoss = out + OUT_ELEMS;
    float* outEnt  = outLoss + 1;
    float* enc     = outEnt + 1;

    cudaMemsetAsync(enc, 0, ENC_ELEMS * sizeof(float), 0);
    zero_kernel<<<1, 1024>>>();
    transpose_kernel<<<dim3(Ddim / 32, Kcode / 32), dim3(32, 8)>>>(weight);
    wn2_kernel<<<Kcode, 32>>>(weight);
    argmin_kernel<<<Ntok / BM, 128>>>(input);
    writer_kernel<<<Ntok / 32, 256>>>(input, weight, out);
    ones_kernel<<<Ntok / 256, 256>>>(enc);
    finalize_kernel<<<1, 256>>>(outLoss, outEnt);
}

// round 4
// speedup vs baseline: 1.7734x; 1.7673x over previous
#include <cuda_runtime.h>
#include <cuda_fp16.h>
#include <cstdint>

#define HW    1024
#define Ntok  32768
#define Kcode 1024
#define Ddim  256
#define OUT_ELEMS ((size_t)8388608)
#define KEXT  768                       // [h1 | h1 | h2] x [g1 | g2 | g1]
#define AEXT_BYTE_OFF 33554560          // align128((OUT_ELEMS+2)*4), inside enc region

__device__ __align__(128) __half g_Bext[Kcode * KEXT];   // 1.5 MB
__device__ float  g_wn2[Kcode];
__device__ unsigned long long g_best[Ntok];              // packed (ordFloat(score)<<32 | 1023-idx)
__device__ int    g_idx[Ntok];
__device__ int    g_counts[Kcode];
__device__ double g_loss;

// ---------------- PTX helpers ----------------
__device__ __forceinline__ uint32_t smem_u32(const void* p) {
    uint32_t a;
    asm("{ .reg .u64 t; cvta.to.shared.u64 t, %1; cvt.u32.u64 %0, t; }" : "=r"(a) : "l"(p));
    return a;
}
#define CP_ASYNC16(dst, src) \
    asm volatile("cp.async.cg.shared.global [%0], [%1], 16;" :: "r"(dst), "l"(src) : "memory")
#define CP_COMMIT() asm volatile("cp.async.commit_group;" ::: "memory")
#define CP_WAIT2()  asm volatile("cp.async.wait_group 2;" ::: "memory")

#define LDMATRIX_X4(r0, r1, r2, r3, addr) \
    asm volatile("ldmatrix.sync.aligned.m8n8.x4.shared.b16 {%0,%1,%2,%3}, [%4];" \
        : "=r"(r0), "=r"(r1), "=r"(r2), "=r"(r3) : "r"(addr))

#define MMA16816(c0, c1, c2, c3, a0, a1, a2, a3, b0, b1) \
    asm volatile("mma.sync.aligned.m16n8k16.row.col.f32.f16.f16.f32 " \
        "{%0,%1,%2,%3}, {%4,%5,%6,%7}, {%8,%9}, {%0,%1,%2,%3};" \
        : "+f"(c0), "+f"(c1), "+f"(c2), "+f"(c3) \
        : "r"(a0), "r"(a1), "r"(a2), "r"(a3), "r"(b0), "r"(b1))

// ---------------- zero / idempotency ----------------
__global__ void zero_kernel() {
    const int i = blockIdx.x * 1024 + threadIdx.x;   // grid 32 x 1024
    if (i < Ntok)  g_best[i] = 0ull;
    if (i < Kcode) g_counts[i] = 0;
    if (i == 0)    g_loss = 0.0;
}

// ---------------- B digits + ||w||^2 ----------------
__global__ void convB_kernel(const float* __restrict__ weight) {
    __shared__ float red[64];
    const int k = blockIdx.x, tid = threadIdx.x;   // 1024 blocks x 64
    float s = 0.f;
    __half* dst = g_Bext + (size_t)k * KEXT;
    for (int d = tid; d < Ddim; d += 64) {
        float x = weight[(size_t)k * Ddim + d];
        s += x * x;
        __half g1 = __float2half_rn(x);
        float r1 = x - __half2float(g1);
        __half g2 = __float2half_rn(r1);
        dst[d] = g1; dst[256 + d] = g2; dst[512 + d] = g1;   // [g1|g2|g1]
    }
    red[tid] = s; __syncthreads();
    for (int o = 32; o > 0; o >>= 1) { if (tid < o) red[tid] += red[tid + o]; __syncthreads(); }
    if (tid == 0) g_wn2[k] = red[0];
}

// ---------------- A digits: 32 tokens/block, pattern [h1|h1|h2] ----------------
__global__ void __launch_bounds__(256) convA_kernel(const float* __restrict__ input,
                                                    __half* __restrict__ Aext) {
    __shared__ __half h[2][32][264];   // 264 halves/row => 528B, 16B-multiple
    const int tid = threadIdx.x, lane = tid & 31, dg = tid >> 5;
    const int n0 = blockIdx.x * 32;
    const int b = n0 / HW, hw0 = n0 % HW;
    const float* ib = input + (size_t)b * Ddim * HW + hw0;
    for (int d = dg; d < Ddim; d += 8) {
        float x = ib[(size_t)d * HW + lane];
        __half h1 = __float2half_rn(x);
        float r1 = x - __half2float(h1);
        h[0][lane][d] = h1;
        h[1][lane][d] = __float2half_rn(r1);
    }
    __syncthreads();
    // write 32 rows x 96 16B-chunks
    for (int o = tid; o < 32 * 96; o += 256) {
        const int row = o / 96, s16 = o % 96;
        const int kext = s16 * 8, seg = kext >> 8, dsrc = kext & 255;
        const int dig = (seg == 2) ? 1 : 0;
        const uint4 v = *(const uint4*)&h[dig][row][dsrc];
        *(uint4*)((char*)Aext + (size_t)(n0 + row) * (KEXT * 2) + s16 * 16) = v;
    }
}

// ---------------- HMMA GEMM + fused per-chunk argmax ----------------
// grid (256, 8): x = 128-token tile, y = 128-code chunk. 256 threads (8 warps).
// CTA tile M128 x N128, K=768, BK=64 (12 stages), 3-slot cp.async ring.
// smem: [sb, sb+3*32768) slots (A 16KB | B 16KB each), [sb+98304, +512) wn2 chunk
#define SMEM_TOTAL (1024 + 3 * 32768 + 512)

__device__ __forceinline__ void fill_stage(uint32_t sb, const char* Aab, const char* Bgb,
                                           int tid, int g) {
    const int slot = g % 3;
    const uint32_t SA = sb + slot * 32768;
    const uint32_t SB = SA + 16384;
    const char* As = Aab + (size_t)g * 128;
    const char* Bs = Bgb + (size_t)g * 128;
    #pragma unroll
    for (int o = 0; o < 4; o++) {
        const int idx = tid + o * 256, row = idx >> 3, c16 = idx & 7;
        const uint32_t sw = (uint32_t)(c16 * 16) ^ (uint32_t)((row & 7) * 16);
        CP_ASYNC16(SA + row * 128 + sw, As + (size_t)row * (KEXT * 2) + c16 * 16);
        CP_ASYNC16(SB + row * 128 + sw, Bs + (size_t)row * (KEXT * 2) + c16 * 16);
    }
}

__device__ __forceinline__ void amax(float& bv, int& bi, float v, int i) {
    if (v > bv || (v == bv && i < bi)) { bv = v; bi = i; }
}

__global__ void __launch_bounds__(256, 2) gemm_kernel(const __half* __restrict__ Aext) {
    extern __shared__ char smem[];
    const uint32_t sbr = smem_u32(smem);
    const uint32_t sb = (sbr + 1023) & ~1023u;
    float* swn = (float*)(smem + (sb - sbr) + 3 * 32768);

    const int tid = threadIdx.x, warp = tid >> 5, lane = tid & 31;
    const int n0 = blockIdx.x * 128;          // token base
    const int cbase = blockIdx.y * 128;       // code base
    const char* Aab = (const char*)Aext + (size_t)n0 * (KEXT * 2);
    const char* Bgb = (const char*)g_Bext + (size_t)cbase * (KEXT * 2);

    if (tid < 128) swn[tid] = g_wn2[cbase + tid];

    // prologue
    fill_stage(sb, Aab, Bgb, tid, 0); CP_COMMIT();
    fill_stage(sb, Aab, Bgb, tid, 1); CP_COMMIT();
    fill_stage(sb, Aab, Bgb, tid, 2); CP_COMMIT();

    float c[16][4];
    #pragma unroll
    for (int nt = 0; nt < 16; nt++)
        #pragma unroll
        for (int j = 0; j < 4; j++) c[nt][j] = 0.f;

    // per-lane ldmatrix addressing
    const int wrow0 = warp * 16;
    const int arow = wrow0 + (lane & 15);
    const uint32_t aswz = (uint32_t)((arow & 7) * 16);
    const uint32_t aLow = (uint32_t)((lane >> 4) << 4);          // 0 or 16
    const int browL = ((lane >> 4) & 1) * 8 + (lane & 7);        // row within 16-row pair
    const uint32_t bswz = (uint32_t)((lane & 7) * 16);
    const uint32_t bKb = (uint32_t)(((lane >> 3) & 1) * 16);     // 0 or 16

    for (int g = 0; g < 12; g++) {
        CP_WAIT2();
        __syncthreads();
        const uint32_t SA = sb + (g % 3) * 32768;
        const uint32_t SB = SA + 16384;
        const uint32_t aBase = SA + arow * 128;
        #pragma unroll
        for (int k16 = 0; k16 < 4; k16++) {
            uint32_t a0, a1, a2, a3;
            LDMATRIX_X4(a0, a1, a2, a3, aBase + (((uint32_t)(k16 * 32) + aLow) ^ aswz));
            #pragma unroll
            for (int ntp = 0; ntp < 8; ntp++) {
                uint32_t b0, b1, b2, b3;
                const uint32_t bAddr = SB + (uint32_t)(ntp * 16 + browL) * 128 +
                                       (((uint32_t)(k16 * 32) + bKb) ^ bswz);
                LDMATRIX_X4(b0, b1, b2, b3, bAddr);
                MMA16816(c[2 * ntp][0], c[2 * ntp][1], c[2 * ntp][2], c[2 * ntp][3],
                         a0, a1, a2, a3, b0, b1);
                MMA16816(c[2 * ntp + 1][0], c[2 * ntp + 1][1], c[2 * ntp + 1][2], c[2 * ntp + 1][3],
                         a0, a1, a2, a3, b2, b3);
            }
        }
        __syncthreads();
        if (g + 3 < 12) fill_stage(sb, Aab, Bgb, tid, g + 3);
        CP_COMMIT();
    }

    // epilogue: per-token argmax over this chunk's 128 codes
    float bv0 = -3.4e38f, bv1 = -3.4e38f;
    int bi0 = 0, bi1 = 0;
    const int colq = (lane & 3) * 2;
    #pragma unroll
    for (int nt = 0; nt < 16; nt++) {
        const int cc = nt * 8 + colq;
        const float w0 = swn[cc], w1 = swn[cc + 1];
        amax(bv0, bi0, 2.f * c[nt][0] - w0, cc);
        amax(bv0, bi0, 2.f * c[nt][1] - w1, cc + 1);
        amax(bv1, bi1, 2.f * c[nt][2] - w0, cc);
        amax(bv1, bi1, 2.f * c[nt][3] - w1, cc + 1);
    }
    // reduce across the 4 lanes sharing each row
    #pragma unroll
    for (int x = 1; x <= 2; x <<= 1) {
        float ov0 = __shfl_xor_sync(0xffffffffu, bv0, x);
        int   oi0 = __shfl_xor_sync(0xffffffffu, bi0, x);
        float ov1 = __shfl_xor_sync(0xffffffffu, bv1, x);
        int   oi1 = __shfl_xor_sync(0xffffffffu, bi1, x);
        amax(bv0, bi0, ov0, oi0);
        amax(bv1, bi1, ov1, oi1);
    }
    if ((lane & 3) == 0) {
        const int r = wrow0 + (lane >> 2);
        const int t0 = n0 + r, t1 = t0 + 8;
        unsigned int f0 = __float_as_uint(bv0);
        unsigned int o0 = (f0 & 0x80000000u) ? ~f0 : (f0 | 0x80000000u);
        unsigned int f1 = __float_as_uint(bv1);
        unsigned int o1 = (f1 & 0x80000000u) ? ~f1 : (f1 | 0x80000000u);
        atomicMax(&g_best[t0], ((unsigned long long)o0 << 32) |
                               (unsigned long long)(unsigned)(1023 - (cbase + bi0)));
        atomicMax(&g_best[t1], ((unsigned long long)o1 << 32) |
                               (unsigned long long)(unsigned)(1023 - (cbase + bi1)));
    }
}

// ---------------- decode argmin + histogram ----------------
__global__ void idx_kernel() {
    const int n = blockIdx.x * 256 + threadIdx.x;   // grid 128 x 256
    if (n < Ntok) {
        const int ix = 1023 - (int)(unsigned int)g_best[n];
        g_idx[n] = ix;
        atomicAdd(&g_counts[ix], 1);
    }
}

// ---------------- encodings: write full one-hot rows (replaces memset+scatter) ----------------
__global__ void enc_kernel(float* __restrict__ enc) {
    const int n = blockIdx.x;                 // 32768 blocks x 256 threads
    const int tid = threadIdx.x;
    const int ix = g_idx[n];
    float2* row = (float2*)(enc + (size_t)n * Kcode);
    #pragma unroll
    for (int o = 0; o < 2; o++) {
        const int e2 = tid + o * 256;          // 512 float2 per row
        float2 v = make_float2(0.f, 0.f);
        if ((ix >> 1) == e2) { if (ix & 1) v.y = 1.f; else v.x = 1.f; }
        row[e2] = v;
    }
}

// ---------------- gather -> out (BCHW) + commitment loss ----------------
__global__ void writer_kernel(const float* __restrict__ input,
                              const float* __restrict__ weight,
                              float* __restrict__ out) {
    const int tid = threadIdx.x;
    const int n0 = blockIdx.x * 32;
    const int b = n0 / HW, hw0 = n0 % HW;
    __shared__ int sidx[32];
    __shared__ float q[32][257];
    if (tid < 32) sidx[tid] = g_idx[n0 + tid];
    __syncthreads();
    for (int e4 = tid; e4 < 32 * (Ddim / 4); e4 += 256) {
        const int t = e4 >> 6, d4 = (e4 & 63) * 4;
        float4 v = *(const float4*)&weight[(size_t)sidx[t] * Ddim + d4];
        q[t][d4] = v.x; q[t][d4 + 1] = v.y; q[t][d4 + 2] = v.z; q[t][d4 + 3] = v.w;
    }
    __syncthreads();
    const int lane = tid & 31, cg = tid >> 5;
    const float* xb = input + (size_t)b * Ddim * HW;
    float* ob = out + (size_t)b * Ddim * HW;
    float lsum = 0.f;
    for (int ch = cg; ch < Ddim; ch += 8) {
        const float qv = q[lane][ch];
        const float xv = xb[(size_t)ch * HW + hw0 + lane];
        ob[(size_t)ch * HW + hw0 + lane] = qv;
        const float df = qv - xv;
        lsum += df * df;
    }
    __shared__ float rbuf[256];
    rbuf[tid] = lsum; __syncthreads();
    for (int o = 128; o > 0; o >>= 1) { if (tid < o) rbuf[tid] += rbuf[tid + o]; __syncthreads(); }
    if (tid == 0) atomicAdd(&g_loss, (double)rbuf[0]);
}

__global__ void finalize_kernel(float* __restrict__ outLoss, float* __restrict__ outEnt) {
    __shared__ double sh[256];
    const int tid = threadIdx.x;
    double s = 0.0;
    for (int k = tid; k < Kcode; k += 256) {
        const float p = (float)g_counts[k] * (1.0f / (float)Ntok);
        s += (double)(p * logf(p + 1e-10f));
    }
    sh[tid] = s; __syncthreads();
    for (int o = 128; o > 0; o >>= 1) { if (tid < o) sh[tid] += sh[tid + o]; __syncthreads(); }
    if (tid == 0) {
        outEnt[0]  = (float)(-sh[0]);
        outLoss[0] = (float)(0.25 * g_loss / (double)((size_t)Ntok * Ddim));
    }
}

// ---------------- launch ----------------
extern "C" void kernel_launch(void* const* d_in, const int* in_sizes, int n_in,
                              void* d_out, int out_size) {
    const float* input  = (const float*)d_in[0];
    const float* weight = (const float*)d_in[1];
    float* out     = (float*)d_out;
    float* outLoss = out + OUT_ELEMS;
    float* outEnt  = outLoss + 1;
    float* enc     = outEnt + 1;
    __half* Aext   = (__half*)((char*)d_out + AEXT_BYTE_OFF);  // scratch inside enc region

    static int attr_done = 0;
    if (!attr_done) {
        cudaFuncSetAttribute(gemm_kernel, cudaFuncAttributeMaxDynamicSharedMemorySize, SMEM_TOTAL);
        attr_done = 1;
    }

    zero_kernel<<<32, 1024>>>();
    convB_kernel<<<Kcode, 64>>>(weight);
    convA_kernel<<<Ntok / 32, 256>>>(input, Aext);
    gemm_kernel<<<dim3(256, 8), 256, SMEM_TOTAL>>>(Aext);
    idx_kernel<<<128, 256>>>();
    enc_kernel<<<Ntok, 256>>>(enc);        // overwrites Aext region — must follow gemm
    writer_kernel<<<Ntok / 32, 256>>>(input, weight, out);
    finalize_kernel<<<1, 256>>>(outLoss, outEnt);
}

// round 5
// speedup vs baseline: 1.8924x; 1.0671x over previous
#include <cuda_runtime.h>
#include <cuda_fp16.h>
#include <cstdint>

#define HW    1024
#define Ntok  32768
#define Kcode 1024
#define Ddim  256
#define OUT_ELEMS ((size_t)8388608)
#define KEXT  768                       // [h1 | h1 | h2] x [g1 | g2 | g1]
#define AEXT_BYTE_OFF 33554560          // align128((OUT_ELEMS+2)*4), inside enc region

__device__ __align__(128) __half g_Bext[Kcode * KEXT];   // 1.5 MB
__device__ float  g_wn2[Kcode];
__device__ unsigned long long g_best[Ntok];              // packed (ordFloat(score)<<32 | 1023-idx)
__device__ int    g_idx[Ntok];
__device__ int    g_counts[Kcode];
__device__ double g_loss;

// ---------------- PTX helpers ----------------
__device__ __forceinline__ uint32_t smem_u32(const void* p) {
    uint32_t a;
    asm("{ .reg .u64 t; cvta.to.shared.u64 t, %1; cvt.u32.u64 %0, t; }" : "=r"(a) : "l"(p));
    return a;
}
#define CP_ASYNC16(dst, src) \
    asm volatile("cp.async.cg.shared.global [%0], [%1], 16;" :: "r"(dst), "l"(src) : "memory")
#define CP_COMMIT() asm volatile("cp.async.commit_group;" ::: "memory")
#define CP_WAIT2()  asm volatile("cp.async.wait_group 2;" ::: "memory")

#define LDMATRIX_X4(r0, r1, r2, r3, addr) \
    asm volatile("ldmatrix.sync.aligned.m8n8.x4.shared.b16 {%0,%1,%2,%3}, [%4];" \
        : "=r"(r0), "=r"(r1), "=r"(r2), "=r"(r3) : "r"(addr))

#define MMA16816(c0, c1, c2, c3, a0, a1, a2, a3, b0, b1) \
    asm volatile("mma.sync.aligned.m16n8k16.row.col.f32.f16.f16.f32 " \
        "{%0,%1,%2,%3}, {%4,%5,%6,%7}, {%8,%9}, {%0,%1,%2,%3};" \
        : "+f"(c0), "+f"(c1), "+f"(c2), "+f"(c3) \
        : "r"(a0), "r"(a1), "r"(a2), "r"(a3), "r"(b0), "r"(b1))

// ---------------- zero / idempotency ----------------
__global__ void zero_kernel() {
    const int i = blockIdx.x * 1024 + threadIdx.x;   // grid 32 x 1024
    if (i < Ntok)  g_best[i] = 0ull;
    if (i < Kcode) g_counts[i] = 0;
    if (i == 0)    g_loss = 0.0;
}

// ---------------- B digits + ||w||^2 ----------------
__global__ void convB_kernel(const float* __restrict__ weight) {
    __shared__ float red[64];
    const int k = blockIdx.x, tid = threadIdx.x;   // 1024 blocks x 64
    float s = 0.f;
    __half* dst = g_Bext + (size_t)k * KEXT;
    for (int d = tid; d < Ddim; d += 64) {
        float x = weight[(size_t)k * Ddim + d];
        s += x * x;
        __half g1 = __float2half_rn(x);
        float r1 = x - __half2float(g1);
        __half g2 = __float2half_rn(r1);
        dst[d] = g1; dst[256 + d] = g2; dst[512 + d] = g1;   // [g1|g2|g1]
    }
    red[tid] = s; __syncthreads();
    for (int o = 32; o > 0; o >>= 1) { if (tid < o) red[tid] += red[tid + o]; __syncthreads(); }
    if (tid == 0) g_wn2[k] = red[0];
}

// ---------------- A digits: 32 tokens/block, pattern [h1|h1|h2] ----------------
__global__ void __launch_bounds__(256) convA_kernel(const float* __restrict__ input,
                                                    __half* __restrict__ Aext) {
    __shared__ __half h[2][32][264];
    const int tid = threadIdx.x, lane = tid & 31, dg = tid >> 5;
    const int n0 = blockIdx.x * 32;
    const int b = n0 / HW, hw0 = n0 % HW;
    const float* ib = input + (size_t)b * Ddim * HW + hw0;
    for (int d = dg; d < Ddim; d += 8) {
        float x = ib[(size_t)d * HW + lane];
        __half h1 = __float2half_rn(x);
        float r1 = x - __half2float(h1);
        h[0][lane][d] = h1;
        h[1][lane][d] = __float2half_rn(r1);
    }
    __syncthreads();
    for (int o = tid; o < 32 * 96; o += 256) {
        const int row = o / 96, s16 = o % 96;
        const int kext = s16 * 8, seg = kext >> 8, dsrc = kext & 255;
        const int dig = (seg == 2) ? 1 : 0;
        const uint4 v = *(const uint4*)&h[dig][row][dsrc];
        *(uint4*)((char*)Aext + (size_t)(n0 + row) * (KEXT * 2) + s16 * 16) = v;
    }
}

// ---------------- HMMA GEMM + fused per-chunk argmax ----------------
// grid (256, 8): x = 128-token tile, y = 128-code chunk. 8 warps as (4 M) x (2 N):
// warp tile 32 rows x 64 cols -> per k16: 2 A-ldmatrix + 4 B-ldmatrix per 16 MMAs.
#define SMEM_TOTAL (1024 + 3 * 32768 + 512)

__device__ __forceinline__ void fill_stage(uint32_t sb, const char* Aab, const char* Bgb,
                                           int tid, int g) {
    const int slot = g % 3;
    const uint32_t SA = sb + slot * 32768;
    const uint32_t SB = SA + 16384;
    const char* As = Aab + (size_t)g * 128;
    const char* Bs = Bgb + (size_t)g * 128;
    #pragma unroll
    for (int o = 0; o < 4; o++) {
        const int idx = tid + o * 256, row = idx >> 3, c16 = idx & 7;
        const uint32_t sw = (uint32_t)(c16 * 16) ^ (uint32_t)((row & 7) * 16);
        CP_ASYNC16(SA + row * 128 + sw, As + (size_t)row * (KEXT * 2) + c16 * 16);
        CP_ASYNC16(SB + row * 128 + sw, Bs + (size_t)row * (KEXT * 2) + c16 * 16);
    }
}

__device__ __forceinline__ void amax(float& bv, int& bi, float v, int i) {
    if (v > bv || (v == bv && i < bi)) { bv = v; bi = i; }
}

__global__ void __launch_bounds__(256, 2) gemm_kernel(const __half* __restrict__ Aext) {
    extern __shared__ char smem[];
    const uint32_t sbr = smem_u32(smem);
    const uint32_t sb = (sbr + 1023) & ~1023u;
    float* swn = (float*)(smem + (sb - sbr) + 3 * 32768);

    const int tid = threadIdx.x, warp = tid >> 5, lane = tid & 31;
    const int warp_m = warp & 3;       // 4 M-blocks of 32 rows
    const int warp_n = warp >> 2;      // 2 N-blocks of 64 cols
    const int n0 = blockIdx.x * 128;
    const int cbase = blockIdx.y * 128;
    const char* Aab = (const char*)Aext + (size_t)n0 * (KEXT * 2);
    const char* Bgb = (const char*)g_Bext + (size_t)cbase * (KEXT * 2);

    if (tid < 128) swn[tid] = g_wn2[cbase + tid];

    fill_stage(sb, Aab, Bgb, tid, 0); CP_COMMIT();
    fill_stage(sb, Aab, Bgb, tid, 1); CP_COMMIT();
    fill_stage(sb, Aab, Bgb, tid, 2); CP_COMMIT();

    float c[2][8][4];
    #pragma unroll
    for (int mt = 0; mt < 2; mt++)
        #pragma unroll
        for (int nt = 0; nt < 8; nt++)
            #pragma unroll
            for (int j = 0; j < 4; j++) c[mt][nt][j] = 0.f;

    // ldmatrix addressing
    const int arowL = (lane & 15);                              // + warp_m*32 + mt*16
    const uint32_t aLow = (uint32_t)((lane >> 4) << 4);         // 0 or 16 (k-halves)
    const int browL = ((lane >> 4) & 1) * 8 + (lane & 7);       // row within 16-row group
    const uint32_t bKb = (uint32_t)(((lane >> 3) & 1) * 16);
    const uint32_t bswz = (uint32_t)((lane & 7) * 16);

    for (int g = 0; g < 12; g++) {
        CP_WAIT2();
        __syncthreads();
        const uint32_t SA = sb + (g % 3) * 32768;
        const uint32_t SB = SA + 16384;
        #pragma unroll
        for (int k16 = 0; k16 < 4; k16++) {
            const uint32_t kOff = (uint32_t)(k16 * 32);
            uint32_t a[2][4];
            #pragma unroll
            for (int mt = 0; mt < 2; mt++) {
                const int arow = warp_m * 32 + mt * 16 + arowL;
                LDMATRIX_X4(a[mt][0], a[mt][1], a[mt][2], a[mt][3],
                            SA + arow * 128 + ((kOff + aLow) ^ (uint32_t)((arow & 7) * 16)));
            }
            #pragma unroll
            for (int np = 0; np < 4; np++) {          // 4 pairs of n8 tiles
                uint32_t b0, b1, b2, b3;
                const uint32_t brow = (uint32_t)(warp_n * 64 + np * 16 + browL);
                LDMATRIX_X4(b0, b1, b2, b3, SB + brow * 128 + ((kOff + bKb) ^ bswz));
                #pragma unroll
                for (int mt = 0; mt < 2; mt++) {
                    MMA16816(c[mt][2 * np][0], c[mt][2 * np][1], c[mt][2 * np][2], c[mt][2 * np][3],
                             a[mt][0], a[mt][1], a[mt][2], a[mt][3], b0, b1);
                    MMA16816(c[mt][2 * np + 1][0], c[mt][2 * np + 1][1],
                             c[mt][2 * np + 1][2], c[mt][2 * np + 1][3],
                             a[mt][0], a[mt][1], a[mt][2], a[mt][3], b2, b3);
                }
            }
        }
        __syncthreads();
        if (g + 3 < 12) fill_stage(sb, Aab, Bgb, tid, g + 3);
        CP_COMMIT();
    }

    // epilogue: per-token argmax over this warp's 64 codes, merged via atomicMax
    const int colq = warp_n * 64 + (lane & 3) * 2;
    #pragma unroll
    for (int mt = 0; mt < 2; mt++) {
        float bv0 = -3.4e38f, bv1 = -3.4e38f;
        int bi0 = 0, bi1 = 0;
        #pragma unroll
        for (int nt = 0; nt < 8; nt++) {
            const int cc = colq + nt * 8;
            const float w0 = swn[cc], w1 = swn[cc + 1];
            amax(bv0, bi0, 2.f * c[mt][nt][0] - w0, cc);
            amax(bv0, bi0, 2.f * c[mt][nt][1] - w1, cc + 1);
            amax(bv1, bi1, 2.f * c[mt][nt][2] - w0, cc);
            amax(bv1, bi1, 2.f * c[mt][nt][3] - w1, cc + 1);
        }
        #pragma unroll
        for (int x = 1; x <= 2; x <<= 1) {
            float ov0 = __shfl_xor_sync(0xffffffffu, bv0, x);
            int   oi0 = __shfl_xor_sync(0xffffffffu, bi0, x);
            float ov1 = __shfl_xor_sync(0xffffffffu, bv1, x);
            int   oi1 = __shfl_xor_sync(0xffffffffu, bi1, x);
            amax(bv0, bi0, ov0, oi0);
            amax(bv1, bi1, ov1, oi1);
        }
        if ((lane & 3) == 0) {
            const int r = warp_m * 32 + mt * 16 + (lane >> 2);
            const int t0 = n0 + r, t1 = t0 + 8;
            unsigned int f0 = __float_as_uint(bv0);
            unsigned int o0 = (f0 & 0x80000000u) ? ~f0 : (f0 | 0x80000000u);
            unsigned int f1 = __float_as_uint(bv1);
            unsigned int o1 = (f1 & 0x80000000u) ? ~f1 : (f1 | 0x80000000u);
            atomicMax(&g_best[t0], ((unsigned long long)o0 << 32) |
                                   (unsigned long long)(unsigned)(1023 - (cbase + bi0)));
            atomicMax(&g_best[t1], ((unsigned long long)o1 << 32) |
                                   (unsigned long long)(unsigned)(1023 - (cbase + bi1)));
        }
    }
}

// ---------------- encodings + idx decode + histogram (fused) ----------------
__global__ void enc_kernel(float* __restrict__ enc) {
    const int n = blockIdx.x;                 // 32768 blocks x 256 threads
    const int tid = threadIdx.x;
    const int ix = 1023 - (int)(unsigned int)g_best[n];
    if (tid == 0) {
        g_idx[n] = ix;
        atomicAdd(&g_counts[ix], 1);
    }
    float2* row = (float2*)(enc + (size_t)n * Kcode);
    #pragma unroll
    for (int o = 0; o < 2; o++) {
        const int e2 = tid + o * 256;
        float2 v = make_float2(0.f, 0.f);
        if ((ix >> 1) == e2) { if (ix & 1) v.y = 1.f; else v.x = 1.f; }
        row[e2] = v;
    }
}

// ---------------- gather -> out (BCHW) + commitment loss ----------------
__global__ void writer_kernel(const float* __restrict__ input,
                              const float* __restrict__ weight,
                              float* __restrict__ out) {
    const int tid = threadIdx.x;
    const int n0 = blockIdx.x * 32;
    const int b = n0 / HW, hw0 = n0 % HW;
    __shared__ int sidx[32];
    __shared__ float q[32][257];
    if (tid < 32) sidx[tid] = g_idx[n0 + tid];
    __syncthreads();
    for (int e4 = tid; e4 < 32 * (Ddim / 4); e4 += 256) {
        const int t = e4 >> 6, d4 = (e4 & 63) * 4;
        float4 v = *(const float4*)&weight[(size_t)sidx[t] * Ddim + d4];
        q[t][d4] = v.x; q[t][d4 + 1] = v.y; q[t][d4 + 2] = v.z; q[t][d4 + 3] = v.w;
    }
    __syncthreads();
    const int lane = tid & 31, cg = tid >> 5;
    const float* xb = input + (size_t)b * Ddim * HW;
    float* ob = out + (size_t)b * Ddim * HW;
    float lsum = 0.f;
    for (int ch = cg; ch < Ddim; ch += 8) {
        const float qv = q[lane][ch];
        const float xv = xb[(size_t)ch * HW + hw0 + lane];
        ob[(size_t)ch * HW + hw0 + lane] = qv;
        const float df = qv - xv;
        lsum += df * df;
    }
    __shared__ float rbuf[256];
    rbuf[tid] = lsum; __syncthreads();
    for (int o = 128; o > 0; o >>= 1) { if (tid < o) rbuf[tid] += rbuf[tid + o]; __syncthreads(); }
    if (tid == 0) atomicAdd(&g_loss, (double)rbuf[0]);
}

__global__ void finalize_kernel(float* __restrict__ outLoss, float* __restrict__ outEnt) {
    __shared__ double sh[256];
    const int tid = threadIdx.x;
    double s = 0.0;
    for (int k = tid; k < Kcode; k += 256) {
        const float p = (float)g_counts[k] * (1.0f / (float)Ntok);
        s += (double)(p * logf(p + 1e-10f));
    }
    sh[tid] = s; __syncthreads();
    for (int o = 128; o > 0; o >>= 1) { if (tid < o) sh[tid] += sh[tid + o]; __syncthreads(); }
    if (tid == 0) {
        outEnt[0]  = (float)(-sh[0]);
        outLoss[0] = (float)(0.25 * g_loss / (double)((size_t)Ntok * Ddim));
    }
}

// ---------------- launch ----------------
extern "C" void kernel_launch(void* const* d_in, const int* in_sizes, int n_in,
                              void* d_out, int out_size) {
    const float* input  = (const float*)d_in[0];
    const float* weight = (const float*)d_in[1];
    float* out     = (float*)d_out;
    float* outLoss = out + OUT_ELEMS;
    float* outEnt  = outLoss + 1;
    float* enc     = outEnt + 1;
    __half* Aext   = (__half*)((char*)d_out + AEXT_BYTE_OFF);  // scratch inside enc region

    static int attr_done = 0;
    if (!attr_done) {
        cudaFuncSetAttribute(gemm_kernel, cudaFuncAttributeMaxDynamicSharedMemorySize, SMEM_TOTAL);
        attr_done = 1;
    }

    zero_kernel<<<32, 1024>>>();
    convB_kernel<<<Kcode, 64>>>(weight);
    convA_kernel<<<Ntok / 32, 256>>>(input, Aext);
    gemm_kernel<<<dim3(256, 8), 256, SMEM_TOTAL>>>(Aext);
    enc_kernel<<<Ntok, 256>>>(enc);        // overwrites Aext region — must follow gemm
    writer_kernel<<<Ntok / 32, 256>>>(input, weight, out);
    finalize_kernel<<<1, 256>>>(outLoss, outEnt);
}

// round 6
// speedup vs baseline: 1.9990x; 1.0563x over previous
#include <cuda_runtime.h>
#include <cuda_fp16.h>
#include <cstdint>

#define HW    1024
#define Ntok  32768
#define Kcode 1024
#define Ddim  256
#define OUT_ELEMS ((size_t)8388608)
#define KEXT  768                       // [h1 | h1 | h2] x [g1 | g2 | g1]
#define AEXT_BYTE_OFF 33554560          // align128((OUT_ELEMS+2)*4), inside enc region

__device__ __align__(128) __half g_Bext[Kcode * KEXT];   // 1.5 MB
__device__ float  g_wn2[Kcode];
__device__ unsigned long long g_best[Ntok];              // packed (ordFloat(score)<<32 | 1023-idx)
__device__ int    g_idx[Ntok];
__device__ int    g_counts[Kcode];
__device__ double g_xsum;     // sum ||x||^2
__device__ double g_bsum;     // sum best scores

// ---------------- PTX helpers ----------------
__device__ __forceinline__ uint32_t smem_u32(const void* p) {
    uint32_t a;
    asm("{ .reg .u64 t; cvta.to.shared.u64 t, %1; cvt.u32.u64 %0, t; }" : "=r"(a) : "l"(p));
    return a;
}
#define CP_ASYNC16(dst, src) \
    asm volatile("cp.async.cg.shared.global [%0], [%1], 16;" :: "r"(dst), "l"(src) : "memory")
#define CP_COMMIT() asm volatile("cp.async.commit_group;" ::: "memory")
#define CP_WAIT1()  asm volatile("cp.async.wait_group 1;" ::: "memory")

#define LDMATRIX_X4(r0, r1, r2, r3, addr) \
    asm volatile("ldmatrix.sync.aligned.m8n8.x4.shared.b16 {%0,%1,%2,%3}, [%4];" \
        : "=r"(r0), "=r"(r1), "=r"(r2), "=r"(r3) : "r"(addr))

#define MMA16816(c0, c1, c2, c3, a0, a1, a2, a3, b0, b1) \
    asm volatile("mma.sync.aligned.m16n8k16.row.col.f32.f16.f16.f32 " \
        "{%0,%1,%2,%3}, {%4,%5,%6,%7}, {%8,%9}, {%0,%1,%2,%3};" \
        : "+f"(c0), "+f"(c1), "+f"(c2), "+f"(c3) \
        : "r"(a0), "r"(a1), "r"(a2), "r"(a3), "r"(b0), "r"(b1))

// ---------------- zero / idempotency ----------------
__global__ void zero_kernel() {
    const int i = blockIdx.x * 1024 + threadIdx.x;   // grid 32 x 1024
    if (i < Ntok)  g_best[i] = 0ull;
    if (i < Kcode) g_counts[i] = 0;
    if (i == 0) { g_xsum = 0.0; g_bsum = 0.0; }
}

// ---------------- B digits + ||w||^2 ----------------
__global__ void convB_kernel(const float* __restrict__ weight) {
    __shared__ float red[64];
    const int k = blockIdx.x, tid = threadIdx.x;   // 1024 blocks x 64
    float s = 0.f;
    __half* dst = g_Bext + (size_t)k * KEXT;
    for (int d = tid; d < Ddim; d += 64) {
        float x = weight[(size_t)k * Ddim + d];
        s += x * x;
        __half g1 = __float2half_rn(x);
        float r1 = x - __half2float(g1);
        __half g2 = __float2half_rn(r1);
        dst[d] = g1; dst[256 + d] = g2; dst[512 + d] = g1;   // [g1|g2|g1]
    }
    red[tid] = s; __syncthreads();
    for (int o = 32; o > 0; o >>= 1) { if (tid < o) red[tid] += red[tid + o]; __syncthreads(); }
    if (tid == 0) g_wn2[k] = red[0];
}

// ---------------- A digits + sum||x||^2: 32 tokens/block, pattern [h1|h1|h2] ----------------
__global__ void __launch_bounds__(256) convA_kernel(const float* __restrict__ input,
                                                    __half* __restrict__ Aext) {
    __shared__ __half h[2][32][264];
    __shared__ float xred[256];
    const int tid = threadIdx.x, lane = tid & 31, dg = tid >> 5;
    const int n0 = blockIdx.x * 32;
    const int b = n0 / HW, hw0 = n0 % HW;
    const float* ib = input + (size_t)b * Ddim * HW + hw0;
    float xs = 0.f;
    for (int d = dg; d < Ddim; d += 8) {
        float x = ib[(size_t)d * HW + lane];
        xs += x * x;
        __half h1 = __float2half_rn(x);
        float r1 = x - __half2float(h1);
        h[0][lane][d] = h1;
        h[1][lane][d] = __float2half_rn(r1);
    }
    xred[tid] = xs;
    __syncthreads();
    for (int o = 128; o > 0; o >>= 1) { if (tid < o) xred[tid] += xred[tid + o]; __syncthreads(); }
    if (tid == 0) atomicAdd(&g_xsum, (double)xred[0]);
    for (int o = tid; o < 32 * 96; o += 256) {
        const int row = o / 96, s16 = o % 96;
        const int kext = s16 * 8, seg = kext >> 8, dsrc = kext & 255;
        const int dig = (seg == 2) ? 1 : 0;
        const uint4 v = *(const uint4*)&h[dig][row][dsrc];
        *(uint4*)((char*)Aext + (size_t)(n0 + row) * (KEXT * 2) + s16 * 16) = v;
    }
}

// ---------------- HMMA GEMM + fused per-chunk argmax ----------------
// grid (256, 8). 8 warps as (4 M x 2 N), warp tile 32x64.
// Single-sync multistage pipeline: 3 slots, prefetch depth 2.
#define SMEM_TOTAL (1024 + 3 * 32768 + 512)

__device__ __forceinline__ void fill_stage(uint32_t sb, const char* Aab, const char* Bgb,
                                           int tid, int g) {
    const int slot = g % 3;
    const uint32_t SA = sb + slot * 32768;
    const uint32_t SB = SA + 16384;
    const char* As = Aab + (size_t)g * 128;
    const char* Bs = Bgb + (size_t)g * 128;
    #pragma unroll
    for (int o = 0; o < 4; o++) {
        const int idx = tid + o * 256, row = idx >> 3, c16 = idx & 7;
        const uint32_t sw = (uint32_t)(c16 * 16) ^ (uint32_t)((row & 7) * 16);
        CP_ASYNC16(SA + row * 128 + sw, As + (size_t)row * (KEXT * 2) + c16 * 16);
        CP_ASYNC16(SB + row * 128 + sw, Bs + (size_t)row * (KEXT * 2) + c16 * 16);
    }
}

__device__ __forceinline__ void amax(float& bv, int& bi, float v, int i) {
    if (v > bv || (v == bv && i < bi)) { bv = v; bi = i; }
}

__global__ void __launch_bounds__(256, 2) gemm_kernel(const __half* __restrict__ Aext) {
    extern __shared__ char smem[];
    const uint32_t sbr = smem_u32(smem);
    const uint32_t sb = (sbr + 1023) & ~1023u;
    float* swn = (float*)(smem + (sb - sbr) + 3 * 32768);

    const int tid = threadIdx.x, warp = tid >> 5, lane = tid & 31;
    const int warp_m = warp & 3;
    const int warp_n = warp >> 2;
    const int n0 = blockIdx.x * 128;
    const int cbase = blockIdx.y * 128;
    const char* Aab = (const char*)Aext + (size_t)n0 * (KEXT * 2);
    const char* Bgb = (const char*)g_Bext + (size_t)cbase * (KEXT * 2);

    if (tid < 128) swn[tid] = g_wn2[cbase + tid];

    fill_stage(sb, Aab, Bgb, tid, 0); CP_COMMIT();
    fill_stage(sb, Aab, Bgb, tid, 1); CP_COMMIT();

    float c[2][8][4];
    #pragma unroll
    for (int mt = 0; mt < 2; mt++)
        #pragma unroll
        for (int nt = 0; nt < 8; nt++)
            #pragma unroll
            for (int j = 0; j < 4; j++) c[mt][nt][j] = 0.f;

    const int arowL = (lane & 15);
    const uint32_t aLow = (uint32_t)((lane >> 4) << 4);
    const int browL = ((lane >> 4) & 1) * 8 + (lane & 7);
    const uint32_t bKb = (uint32_t)(((lane >> 3) & 1) * 16);
    const uint32_t bswz = (uint32_t)((lane & 7) * 16);

    for (int g = 0; g < 12; g++) {
        CP_WAIT1();
        __syncthreads();
        if (g + 2 < 12) fill_stage(sb, Aab, Bgb, tid, g + 2);
        CP_COMMIT();
        const uint32_t SA = sb + (g % 3) * 32768;
        const uint32_t SB = SA + 16384;
        #pragma unroll
        for (int k16 = 0; k16 < 4; k16++) {
            const uint32_t kOff = (uint32_t)(k16 * 32);
            uint32_t a[2][4];
            #pragma unroll
            for (int mt = 0; mt < 2; mt++) {
                const int arow = warp_m * 32 + mt * 16 + arowL;
                LDMATRIX_X4(a[mt][0], a[mt][1], a[mt][2], a[mt][3],
                            SA + arow * 128 + ((kOff + aLow) ^ (uint32_t)((arow & 7) * 16)));
            }
            #pragma unroll
            for (int np = 0; np < 4; np++) {
                uint32_t b0, b1, b2, b3;
                const uint32_t brow = (uint32_t)(warp_n * 64 + np * 16 + browL);
                LDMATRIX_X4(b0, b1, b2, b3, SB + brow * 128 + ((kOff + bKb) ^ bswz));
                #pragma unroll
                for (int mt = 0; mt < 2; mt++) {
                    MMA16816(c[mt][2 * np][0], c[mt][2 * np][1], c[mt][2 * np][2], c[mt][2 * np][3],
                             a[mt][0], a[mt][1], a[mt][2], a[mt][3], b0, b1);
                    MMA16816(c[mt][2 * np + 1][0], c[mt][2 * np + 1][1],
                             c[mt][2 * np + 1][2], c[mt][2 * np + 1][3],
                             a[mt][0], a[mt][1], a[mt][2], a[mt][3], b2, b3);
                }
            }
        }
    }

    // epilogue: per-token argmax over this warp's 64 codes, merged via atomicMax
    const int colq = warp_n * 64 + (lane & 3) * 2;
    #pragma unroll
    for (int mt = 0; mt < 2; mt++) {
        float bv0 = -3.4e38f, bv1 = -3.4e38f;
        int bi0 = 0, bi1 = 0;
        #pragma unroll
        for (int nt = 0; nt < 8; nt++) {
            const int cc = colq + nt * 8;
            const float w0 = swn[cc], w1 = swn[cc + 1];
            amax(bv0, bi0, 2.f * c[mt][nt][0] - w0, cc);
            amax(bv0, bi0, 2.f * c[mt][nt][1] - w1, cc + 1);
            amax(bv1, bi1, 2.f * c[mt][nt][2] - w0, cc);
            amax(bv1, bi1, 2.f * c[mt][nt][3] - w1, cc + 1);
        }
        #pragma unroll
        for (int x = 1; x <= 2; x <<= 1) {
            float ov0 = __shfl_xor_sync(0xffffffffu, bv0, x);
            int   oi0 = __shfl_xor_sync(0xffffffffu, bi0, x);
            float ov1 = __shfl_xor_sync(0xffffffffu, bv1, x);
            int   oi1 = __shfl_xor_sync(0xffffffffu, bi1, x);
            amax(bv0, bi0, ov0, oi0);
            amax(bv1, bi1, ov1, oi1);
        }
        if ((lane & 3) == 0) {
            const int r = warp_m * 32 + mt * 16 + (lane >> 2);
            const int t0 = n0 + r, t1 = t0 + 8;
            unsigned int f0 = __float_as_uint(bv0);
            unsigned int o0 = (f0 & 0x80000000u) ? ~f0 : (f0 | 0x80000000u);
            unsigned int f1 = __float_as_uint(bv1);
            unsigned int o1 = (f1 & 0x80000000u) ? ~f1 : (f1 | 0x80000000u);
            atomicMax(&g_best[t0], ((unsigned long long)o0 << 32) |
                                   (unsigned long long)(unsigned)(1023 - (cbase + bi0)));
            atomicMax(&g_best[t1], ((unsigned long long)o1 << 32) |
                                   (unsigned long long)(unsigned)(1023 - (cbase + bi1)));
        }
    }
}

// ---------------- decode + encodings + histogram + bestscore sum ----------------
// 256 blocks x 256 threads; each block owns 128 rows.
__global__ void __launch_bounds__(256) enc_kernel(float* __restrict__ enc) {
    const int tid = threadIdx.x;
    const int base = blockIdx.x * 128;
    __shared__ int six[128];
    __shared__ float sred[128];
    if (tid < 128) {
        const unsigned long long p = g_best[base + tid];
        const unsigned int o = (unsigned int)(p >> 32);
        const float bv = (o & 0x80000000u) ? __uint_as_float(o & 0x7FFFFFFFu)
                                           : __uint_as_float(~o);
        const int ix = 1023 - (int)(unsigned int)(p & 0xFFFFFFFFu);
        six[tid] = ix;
        g_idx[base + tid] = ix;
        atomicAdd(&g_counts[ix], 1);
        sred[tid] = bv;
    }
    __syncthreads();
    for (int o = 64; o > 0; o >>= 1) {
        if (tid < o) sred[tid] += sred[tid + o];
        __syncthreads();
    }
    if (tid == 0) atomicAdd(&g_bsum, (double)sred[0]);
    // stream-zero the 128 rows (enc is 8B-aligned -> float2)
    const float2 z = make_float2(0.f, 0.f);
    float2* r2 = (float2*)(enc + (size_t)base * Kcode);
    #pragma unroll 4
    for (int i = tid; i < 128 * 512; i += 256) r2[i] = z;
    __syncthreads();
    if (tid < 128) enc[(size_t)(base + tid) * Kcode + six[tid]] = 1.0f;
}

// ---------------- gather -> out (BCHW), no input read ----------------
__global__ void writer_kernel(const float* __restrict__ weight,
                              float* __restrict__ out) {
    const int tid = threadIdx.x;
    const int n0 = blockIdx.x * 32;
    const int b = n0 / HW, hw0 = n0 % HW;
    __shared__ int sidx[32];
    __shared__ float q[32][257];
    if (tid < 32) sidx[tid] = g_idx[n0 + tid];
    __syncthreads();
    for (int e4 = tid; e4 < 32 * (Ddim / 4); e4 += 256) {
        const int t = e4 >> 6, d4 = (e4 & 63) * 4;
        float4 v = *(const float4*)&weight[(size_t)sidx[t] * Ddim + d4];
        q[t][d4] = v.x; q[t][d4 + 1] = v.y; q[t][d4 + 2] = v.z; q[t][d4 + 3] = v.w;
    }
    __syncthreads();
    const int lane = tid & 31, cg = tid >> 5;
    float* ob = out + (size_t)b * Ddim * HW;
    #pragma unroll 4
    for (int ch = cg; ch < Ddim; ch += 8)
        ob[(size_t)ch * HW + hw0 + lane] = q[lane][ch];
}

__global__ void finalize_kernel(float* __restrict__ outLoss, float* __restrict__ outEnt) {
    __shared__ double sh[256];
    const int tid = threadIdx.x;
    double s = 0.0;
    for (int k = tid; k < Kcode; k += 256) {
        const float p = (float)g_counts[k] * (1.0f / (float)Ntok);
        s += (double)(p * logf(p + 1e-10f));
    }
    sh[tid] = s; __syncthreads();
    for (int o = 128; o > 0; o >>= 1) { if (tid < o) sh[tid] += sh[tid + o]; __syncthreads(); }
    if (tid == 0) {
        outEnt[0]  = (float)(-sh[0]);
        outLoss[0] = (float)(0.25 * (g_xsum - g_bsum) / (double)((size_t)Ntok * Ddim));
    }
}

// ---------------- launch ----------------
extern "C" void kernel_launch(void* const* d_in, const int* in_sizes, int n_in,
                              void* d_out, int out_size) {
    const float* input  = (const float*)d_in[0];
    const float* weight = (const float*)d_in[1];
    float* out     = (float*)d_out;
    float* outLoss = out + OUT_ELEMS;
    float* outEnt  = outLoss + 1;
    float* enc     = outEnt + 1;
    __half* Aext   = (__half*)((char*)d_out + AEXT_BYTE_OFF);  // scratch inside enc region

    static int attr_done = 0;
    if (!attr_done) {
        cudaFuncSetAttribute(gemm_kernel, cudaFuncAttributeMaxDynamicSharedMemorySize, SMEM_TOTAL);
        attr_done = 1;
    }

    zero_kernel<<<32, 1024>>>();
    convB_kernel<<<Kcode, 64>>>(weight);
    convA_kernel<<<Ntok / 32, 256>>>(input, Aext);
    gemm_kernel<<<dim3(256, 8), 256, SMEM_TOTAL>>>(Aext);
    enc_kernel<<<Ntok / 128, 256>>>(enc);   // overwrites Aext region — must follow gemm
    writer_kernel<<<Ntok / 32, 256>>>(weight, out);
    finalize_kernel<<<1, 256>>>(outLoss, outEnt);
}

// round 8
// speedup vs baseline: 2.2646x; 1.1329x over previous
#include <cuda_runtime.h>
#include <cuda_fp16.h>
#include <cstdint>

#define HW    1024
#define Ntok  32768
#define Kcode 1024
#define Ddim  256
#define OUT_ELEMS ((size_t)8388608)
#define AEXT_BYTE_OFF   33554560ULL                               // align128((OUT_ELEMS+2)*4)
#define SCORE_BYTE_OFF  (AEXT_BYTE_OFF + (size_t)Ntok * 512 * 2)  // Aext is 32 MB

__device__ __align__(128) __half g_Bg[Kcode * 256];   // g1 digits, 512 KB
__device__ float  g_wn2[Kcode];
__device__ float  g_xn[Ntok];          // per-token ||x||
__device__ int    g_gn2max;            // max ||g||^2 as float bits
__device__ int    g_idx[Ntok];
__device__ int    g_counts[Kcode];
__device__ double g_xsum, g_bsum;

// ---------------- PTX helpers ----------------
__device__ __forceinline__ uint32_t smem_u32(const void* p) {
    uint32_t a;
    asm("{ .reg .u64 t; cvta.to.shared.u64 t, %1; cvt.u32.u64 %0, t; }" : "=r"(a) : "l"(p));
    return a;
}
#define CP_ASYNC16(dst, src) \
    asm volatile("cp.async.cg.shared.global [%0], [%1], 16;" :: "r"(dst), "l"(src) : "memory")
#define CP_COMMIT() asm volatile("cp.async.commit_group;" ::: "memory")
#define CP_WAIT1()  asm volatile("cp.async.wait_group 1;" ::: "memory")

#define LDMATRIX_X4(r0, r1, r2, r3, addr) \
    asm volatile("ldmatrix.sync.aligned.m8n8.x4.shared.b16 {%0,%1,%2,%3}, [%4];" \
        : "=r"(r0), "=r"(r1), "=r"(r2), "=r"(r3) : "r"(addr))

#define MMA16816(c0, c1, c2, c3, a0, a1, a2, a3, b0, b1) \
    asm volatile("mma.sync.aligned.m16n8k16.row.col.f32.f16.f16.f32 " \
        "{%0,%1,%2,%3}, {%4,%5,%6,%7}, {%8,%9}, {%0,%1,%2,%3};" \
        : "+f"(c0), "+f"(c1), "+f"(c2), "+f"(c3) \
        : "r"(a0), "r"(a1), "r"(a2), "r"(a3), "r"(b0), "r"(b1))

// ---------------- zero / idempotency ----------------
__global__ void zero_kernel() {
    const int t = threadIdx.x;
    if (t < Kcode) g_counts[t] = 0;
    if (t == 0) { g_xsum = 0.0; g_bsum = 0.0; g_gn2max = 0; }
}

// ---------------- B: g1 digit + ||w||^2 + max||w||^2 ----------------
__global__ void convB_kernel(const float* __restrict__ weight) {
    __shared__ float red[64];
    const int k = blockIdx.x, tid = threadIdx.x;   // 1024 x 64
    float s = 0.f;
    __half* dst = g_Bg + (size_t)k * 256;
    for (int d = tid; d < Ddim; d += 64) {
        float x = weight[(size_t)k * Ddim + d];
        s += x * x;
        dst[d] = __float2half_rn(x);
    }
    red[tid] = s; __syncthreads();
    for (int o = 32; o > 0; o >>= 1) { if (tid < o) red[tid] += red[tid + o]; __syncthreads(); }
    if (tid == 0) {
        g_wn2[k] = red[0];
        atomicMax(&g_gn2max, __float_as_int(red[0]));   // positive floats: bit-monotone
    }
}

// ---------------- A: [h1|h2] digits + per-token ||x|| + sum||x||^2 ----------------
__global__ void __launch_bounds__(256) convA_kernel(const float* __restrict__ input,
                                                    __half* __restrict__ Aext) {
    __shared__ __half h[2][32][264];
    __shared__ float xpart[8][33];
    const int tid = threadIdx.x, lane = tid & 31, dg = tid >> 5;
    const int n0 = blockIdx.x * 32;
    const int b = n0 / HW, hw0 = n0 % HW;
    const float* ib = input + (size_t)b * Ddim * HW + hw0;
    float xs = 0.f;
    for (int d = dg; d < Ddim; d += 8) {
        float x = ib[(size_t)d * HW + lane];
        xs += x * x;
        __half h1 = __float2half_rn(x);
        float r1 = x - __half2float(h1);
        h[0][lane][d] = h1;
        h[1][lane][d] = __float2half_rn(r1);
    }
    xpart[dg][lane] = xs;
    __syncthreads();
    if (tid < 32) {
        float tot = 0.f;
        #pragma unroll
        for (int g = 0; g < 8; g++) tot += xpart[g][tid];
        g_xn[n0 + tid] = sqrtf(tot);
        #pragma unroll
        for (int o = 16; o > 0; o >>= 1) tot += __shfl_down_sync(0xffffffffu, tot, o);
        if (tid == 0) atomicAdd(&g_xsum, (double)tot);
    }
    for (int o = tid; o < 32 * 64; o += 256) {
        const int row = o >> 6, s16 = o & 63;
        const int dig = s16 >> 5, dsrc = (s16 & 31) * 8;
        const uint4 v = *(const uint4*)&h[dig][row][dsrc];
        *(uint4*)((char*)Aext + (size_t)(n0 + row) * 1024 + s16 * 16) = v;
    }
}

// ---------------- coarse HMMA GEMM (K=256, h1 x g1) -> fp16 scores ----------------
// grid (256, 8). 8 warps (4M x 2N), warp tile 32x64, 4 stages BK=64, 3-slot ring.
#define SMEM_TOTAL (1024 + 3 * 32768 + 512)

__device__ __forceinline__ void fill_stage(uint32_t sb, const char* Aab, const char* Bgb,
                                           int tid, int g) {
    const int slot = g % 3;
    const uint32_t SA = sb + slot * 32768;
    const uint32_t SB = SA + 16384;
    const char* As = Aab + g * 128;
    const char* Bs = Bgb + g * 128;
    #pragma unroll
    for (int o = 0; o < 4; o++) {
        const int idx = tid + o * 256, row = idx >> 3, c16 = idx & 7;
        const uint32_t sw = (uint32_t)(c16 * 16) ^ (uint32_t)((row & 7) * 16);
        CP_ASYNC16(SA + row * 128 + sw, As + (size_t)row * 1024 + c16 * 16);  // A pitch 1024B
        CP_ASYNC16(SB + row * 128 + sw, Bs + (size_t)row * 512  + c16 * 16);  // B pitch 512B
    }
}

__global__ void __launch_bounds__(256, 2) gemm_kernel(const __half* __restrict__ Aext,
                                                      __half* __restrict__ scores) {
    extern __shared__ char smem[];
    const uint32_t sbr = smem_u32(smem);
    const uint32_t sb = (sbr + 1023) & ~1023u;
    char* smbase = smem + (sb - sbr);
    float* swn = (float*)(smbase + 3 * 32768);

    const int tid = threadIdx.x, warp = tid >> 5, lane = tid & 31;
    const int warp_m = warp & 3;
    const int warp_n = warp >> 2;
    const int n0 = blockIdx.x * 128;
    const int cbase = blockIdx.y * 128;
    const char* Aab = (const char*)Aext + (size_t)n0 * 1024;
    const char* Bgb = (const char*)g_Bg + (size_t)cbase * 512;

    if (tid < 128) swn[tid] = g_wn2[cbase + tid];

    fill_stage(sb, Aab, Bgb, tid, 0); CP_COMMIT();
    fill_stage(sb, Aab, Bgb, tid, 1); CP_COMMIT();

    float c[2][8][4];
    #pragma unroll
    for (int mt = 0; mt < 2; mt++)
        #pragma unroll
        for (int nt = 0; nt < 8; nt++)
            #pragma unroll
            for (int j = 0; j < 4; j++) c[mt][nt][j] = 0.f;

    const int arowL = (lane & 15);
    const uint32_t aLow = (uint32_t)((lane >> 4) << 4);
    const int browL = ((lane >> 4) & 1) * 8 + (lane & 7);
    const uint32_t bKb = (uint32_t)(((lane >> 3) & 1) * 16);
    const uint32_t bswz = (uint32_t)((lane & 7) * 16);

    for (int g = 0; g < 4; g++) {
        CP_WAIT1();
        __syncthreads();
        if (g + 2 < 4) fill_stage(sb, Aab, Bgb, tid, g + 2);
        CP_COMMIT();
        const uint32_t SA = sb + (g % 3) * 32768;
        const uint32_t SB = SA + 16384;
        #pragma unroll
        for (int k16 = 0; k16 < 4; k16++) {
            const uint32_t kOff = (uint32_t)(k16 * 32);
            uint32_t a[2][4];
            #pragma unroll
            for (int mt = 0; mt < 2; mt++) {
                const int arow = warp_m * 32 + mt * 16 + arowL;
                LDMATRIX_X4(a[mt][0], a[mt][1], a[mt][2], a[mt][3],
                            SA + arow * 128 + ((kOff + aLow) ^ (uint32_t)((arow & 7) * 16)));
            }
            #pragma unroll
            for (int np = 0; np < 4; np++) {
                uint32_t b0, b1, b2, b3;
                const uint32_t brow = (uint32_t)(warp_n * 64 + np * 16 + browL);
                LDMATRIX_X4(b0, b1, b2, b3, SB + brow * 128 + ((kOff + bKb) ^ bswz));
                #pragma unroll
                for (int mt = 0; mt < 2; mt++) {
                    MMA16816(c[mt][2 * np][0], c[mt][2 * np][1], c[mt][2 * np][2], c[mt][2 * np][3],
                             a[mt][0], a[mt][1], a[mt][2], a[mt][3], b0, b1);
                    MMA16816(c[mt][2 * np + 1][0], c[mt][2 * np + 1][1],
                             c[mt][2 * np + 1][2], c[mt][2 * np + 1][3],
                             a[mt][0], a[mt][1], a[mt][2], a[mt][3], b2, b3);
                }
            }
        }
    }

    // epilogue: score = 2*dot - wn2, repack via smem (pitch 66 u32), coalesced store
    __syncthreads();
    uint32_t* sp = (uint32_t*)smbase;
    #pragma unroll
    for (int mt = 0; mt < 2; mt++) {
        const int r0 = warp_m * 32 + mt * 16 + (lane >> 2);
        #pragma unroll
        for (int nt = 0; nt < 8; nt++) {
            const int pp = warp_n * 32 + nt * 4 + (lane & 3);
            const int cc = warp_n * 64 + nt * 8 + (lane & 3) * 2;
            const float w0 = swn[cc], w1 = swn[cc + 1];
            __half2 lo = __floats2half2_rn(2.f * c[mt][nt][0] - w0, 2.f * c[mt][nt][1] - w1);
            __half2 hi = __floats2half2_rn(2.f * c[mt][nt][2] - w0, 2.f * c[mt][nt][3] - w1);
            sp[r0 * 66 + pp]       = *(uint32_t*)&lo;
            sp[(r0 + 8) * 66 + pp] = *(uint32_t*)&hi;
        }
    }
    __syncthreads();
    #pragma unroll
    for (int it = 0; it < 8; it++) {
        const int idx = tid + it * 256;
        const int row = idx >> 4, c16 = idx & 15;
        const uint32_t b0 = row * 66 + c16 * 4;
        uint4 v = make_uint4(sp[b0], sp[b0 + 1], sp[b0 + 2], sp[b0 + 3]);
        *(uint4*)((char*)scores + (size_t)(n0 + row) * 2048 + cbase * 2 + c16 * 16) = v;
    }
}

// ---------------- scan + exact refine: warp per token ----------------
__global__ void __launch_bounds__(256) scan_kernel(const __half* __restrict__ scores,
                                                   const __half* __restrict__ Aext,
                                                   const float* __restrict__ weight) {
    const int tid = threadIdx.x, lane = tid & 31, warp = tid >> 5;
    const int t = blockIdx.x * 8 + warp;

    const uint4* srow = (const uint4*)((const char*)scores + (size_t)t * 2048);
    float sc[4][8];
    #pragma unroll
    for (int i = 0; i < 4; i++) {
        uint4 v = srow[i * 32 + lane];
        uint32_t u[4] = {v.x, v.y, v.z, v.w};
        #pragma unroll
        for (int q = 0; q < 4; q++) {
            float2 f = __half22float2(*(const __half2*)&u[q]);
            sc[i][q * 2] = f.x; sc[i][q * 2 + 1] = f.y;
        }
    }
    float M = -3.4e38f;
    #pragma unroll
    for (int i = 0; i < 4; i++)
        #pragma unroll
        for (int j = 0; j < 8; j++) M = fmaxf(M, sc[i][j]);
    #pragma unroll
    for (int x = 16; x > 0; x >>= 1) M = fmaxf(M, __shfl_xor_sync(0xffffffffu, M, x));

    // rigorous candidate threshold: digit rounding + fp16 storage + slack
    const float gmaxn = sqrtf(__int_as_float(g_gn2max));
    const float T = g_xn[t] * gmaxn * (1.f / 256.f) + 0.004f * fabsf(M) + 0.25f;
    const float thresh = M - T;

    // reconstruct x (error ~2^-22): 8 dims per lane
    float xr[8];
    {
        const __half* xa = Aext + (size_t)t * 512 + lane * 8;
        uint4 v1 = *(const uint4*)xa;
        uint4 v2 = *(const uint4*)(xa + 256);
        const uint32_t* u1 = (const uint32_t*)&v1;
        const uint32_t* u2 = (const uint32_t*)&v2;
        #pragma unroll
        for (int q = 0; q < 4; q++) {
            float2 a = __half22float2(*(const __half2*)&u1[q]);
            float2 b = __half22float2(*(const __half2*)&u2[q]);
            xr[q * 2]     = a.x + b.x;
            xr[q * 2 + 1] = a.y + b.y;
        }
    }

    float bestE = -3.4e38f; int bidx = 0x7FFFFFFF;
    #pragma unroll 1
    for (int i = 0; i < 4; i++) {
        #pragma unroll 1
        for (int j = 0; j < 8; j++) {
            uint32_t bal = __ballot_sync(0xffffffffu, sc[i][j] >= thresh);
            while (bal) {
                const int src = __ffs(bal) - 1;
                bal &= bal - 1;
                const int code = i * 256 + src * 8 + j;
                const float* w = weight + (size_t)code * Ddim + lane * 8;
                float d = 0.f;
                #pragma unroll
                for (int q = 0; q < 8; q++) d = fmaf(xr[q], w[q], d);
                #pragma unroll
                for (int x = 16; x > 0; x >>= 1) d += __shfl_xor_sync(0xffffffffu, d, x);
                const float s = 2.f * d - g_wn2[code];
                if (s > bestE || (s == bestE && code < bidx)) { bestE = s; bidx = code; }
            }
        }
    }
    __shared__ double bsh[8];
    if (lane == 0) {
        g_idx[t] = bidx;
        atomicAdd(&g_counts[bidx], 1);
        bsh[warp] = (double)bestE;
    }
    __syncthreads();
    if (tid == 0) {
        double s = 0.0;
        #pragma unroll
        for (int w8 = 0; w8 < 8; w8++) s += bsh[w8];
        atomicAdd(&g_bsum, s);
    }
}

// ---------------- encodings: zero + scatter (uses g_idx) ----------------
__global__ void __launch_bounds__(256) enc_kernel(float* __restrict__ enc) {
    const int tid = threadIdx.x;
    const int base = blockIdx.x * 128;
    __shared__ int six[128];
    if (tid < 128) six[tid] = g_idx[base + tid];
    __syncthreads();
    const float2 z = make_float2(0.f, 0.f);
    float2* r2 = (float2*)(enc + (size_t)base * Kcode);
    #pragma unroll 4
    for (int i = tid; i < 128 * 512; i += 256) r2[i] = z;
    __syncthreads();
    if (tid < 128) enc[(size_t)(base + tid) * Kcode + six[tid]] = 1.0f;
}

// ---------------- gather -> out (BCHW) ----------------
__global__ void writer_kernel(const float* __restrict__ weight,
                              float* __restrict__ out) {
    const int tid = threadIdx.x;
    const int n0 = blockIdx.x * 32;
    const int b = n0 / HW, hw0 = n0 % HW;
    __shared__ int sidx[32];
    __shared__ float q[32][257];
    if (tid < 32) sidx[tid] = g_idx[n0 + tid];
    __syncthreads();
    for (int e4 = tid; e4 < 32 * (Ddim / 4); e4 += 256) {
        const int t = e4 >> 6, d4 = (e4 & 63) * 4;
        float4 v = *(const float4*)&weight[(size_t)sidx[t] * Ddim + d4];
        q[t][d4] = v.x; q[t][d4 + 1] = v.y; q[t][d4 + 2] = v.z; q[t][d4 + 3] = v.w;
    }
    __syncthreads();
    const int lane = tid & 31, cg = tid >> 5;
    float* ob = out + (size_t)b * Ddim * HW;
    #pragma unroll 4
    for (int ch = cg; ch < Ddim; ch += 8)
        ob[(size_t)ch * HW + hw0 + lane] = q[lane][ch];
}

__global__ void finalize_kernel(float* __restrict__ outLoss, float* __restrict__ outEnt) {
    __shared__ double sh[256];
    const int tid = threadIdx.x;
    double s = 0.0;
    for (int k = tid; k < Kcode; k += 256) {
        const float p = (float)g_counts[k] * (1.0f / (float)Ntok);
        s += (double)(p * logf(p + 1e-10f));
    }
    sh[tid] = s; __syncthreads();
    for (int o = 128; o > 0; o >>= 1) { if (tid < o) sh[tid] += sh[tid + o]; __syncthreads(); }
    if (tid == 0) {
        outEnt[0]  = (float)(-sh[0]);
        outLoss[0] = (float)(0.25 * (g_xsum - g_bsum) / (double)((size_t)Ntok * Ddim));
    }
}

// ---------------- launch ----------------
extern "C" void kernel_launch(void* const* d_in, const int* in_sizes, int n_in,
                              void* d_out, int out_size) {
    const float* input  = (const float*)d_in[0];
    const float* weight = (const float*)d_in[1];
    float* out     = (float*)d_out;
    float* outLoss = out + OUT_ELEMS;
    float* outEnt  = outLoss + 1;
    float* enc     = outEnt + 1;
    __half* Aext   = (__half*)((char*)d_out + AEXT_BYTE_OFF);    // 32 MB scratch in enc region
    __half* scores = (__half*)((char*)d_out + SCORE_BYTE_OFF);   // 64 MB scratch in enc region

    static int attr_done = 0;
    if (!attr_done) {
        cudaFuncSetAttribute(gemm_kernel, cudaFuncAttributeMaxDynamicSharedMemorySize, SMEM_TOTAL);
        attr_done = 1;
    }

    zero_kernel<<<1, 1024>>>();
    convB_kernel<<<Kcode, 64>>>(weight);
    convA_kernel<<<Ntok / 32, 256>>>(input, Aext);
    gemm_kernel<<<dim3(256, 8), 256, SMEM_TOTAL>>>(Aext, scores);
    scan_kernel<<<Ntok / 8, 256>>>(scores, Aext, weight);
    enc_kernel<<<Ntok / 128, 256>>>(enc);    // overwrites Aext/scores region — after scan
    writer_kernel<<<Ntok / 32, 256>>>(weight, out);
    finalize_kernel<<<1, 256>>>(outLoss, outEnt);
}

// round 10
// speedup vs baseline: 2.2922x; 1.0122x over previous
#include <cuda_runtime.h>
#include <cuda_fp16.h>
#include <cstdint>

#define HW    1024
#define Ntok  32768
#define Kcode 1024
#define Ddim  256
#define OUT_ELEMS ((size_t)8388608)

// static scratch (allowed: __device__ globals)
__device__ __align__(128) __half g_Aext[(size_t)Ntok * 512];     // 32 MB  [h1|h2] per token
__device__ __align__(128) __half g_scores[(size_t)Ntok * 1024];  // 64 MB  coarse scores fp16
__device__ __align__(128) __half g_Bg[Kcode * 256];              // g1 digits
__device__ float  g_wn2[Kcode];
__device__ float  g_xn[Ntok];
__device__ int    g_gn2max;
__device__ int    g_counts[Kcode];
__device__ double g_xsum, g_bsum;

// ---------------- PTX helpers ----------------
__device__ __forceinline__ uint32_t smem_u32(const void* p) {
    uint32_t a;
    asm("{ .reg .u64 t; cvta.to.shared.u64 t, %1; cvt.u32.u64 %0, t; }" : "=r"(a) : "l"(p));
    return a;
}
#define CP_ASYNC16(dst, src) \
    asm volatile("cp.async.cg.shared.global [%0], [%1], 16;" :: "r"(dst), "l"(src) : "memory")
#define CP_COMMIT() asm volatile("cp.async.commit_group;" ::: "memory")
#define CP_WAIT1()  asm volatile("cp.async.wait_group 1;" ::: "memory")

#define LDMATRIX_X4(r0, r1, r2, r3, addr) \
    asm volatile("ldmatrix.sync.aligned.m8n8.x4.shared.b16 {%0,%1,%2,%3}, [%4];" \
        : "=r"(r0), "=r"(r1), "=r"(r2), "=r"(r3) : "r"(addr))

#define MMA16816(c0, c1, c2, c3, a0, a1, a2, a3, b0, b1) \
    asm volatile("mma.sync.aligned.m16n8k16.row.col.f32.f16.f16.f32 " \
        "{%0,%1,%2,%3}, {%4,%5,%6,%7}, {%8,%9}, {%0,%1,%2,%3};" \
        : "+f"(c0), "+f"(c1), "+f"(c2), "+f"(c3) \
        : "r"(a0), "r"(a1), "r"(a2), "r"(a3), "r"(b0), "r"(b1))

// ---------------- zero / idempotency ----------------
__global__ void zero_kernel() {
    const int t = threadIdx.x;
    if (t < Kcode) g_counts[t] = 0;
    if (t == 0) { g_xsum = 0.0; g_bsum = 0.0; g_gn2max = 0; }
}

// ---------------- merged conv: blocks [0,1024) = B codes, [1024,2048) = A token-tiles ----
__global__ void __launch_bounds__(256) conv_kernel(const float* __restrict__ weight,
                                                   const float* __restrict__ input) {
    const int tid = threadIdx.x;
    if (blockIdx.x < 1024) {
        // ---- convB: one code per block, 256 threads (one dim each) ----
        __shared__ float red[256];
        const int k = blockIdx.x;
        const float x = weight[(size_t)k * Ddim + tid];
        g_Bg[(size_t)k * 256 + tid] = __float2half_rn(x);
        red[tid] = x * x;
        __syncthreads();
        for (int o = 128; o > 0; o >>= 1) {
            if (tid < o) red[tid] += red[tid + o];
            __syncthreads();
        }
        if (tid == 0) {
            g_wn2[k] = red[0];
            atomicMax(&g_gn2max, __float_as_int(red[0]));  // positive floats: bit-monotone
        }
    } else {
        // ---- convA: 32 tokens per block ----
        __shared__ __half h[2][32][264];
        __shared__ float xpart[8][33];
        const int lane = tid & 31, dg = tid >> 5;
        const int n0 = (blockIdx.x - 1024) * 32;
        const int b = n0 / HW, hw0 = n0 % HW;
        const float* ib = input + (size_t)b * Ddim * HW + hw0;
        float xs = 0.f;
        for (int d = dg; d < Ddim; d += 8) {
            float x = ib[(size_t)d * HW + lane];
            xs += x * x;
            __half h1 = __float2half_rn(x);
            float r1 = x - __half2float(h1);
            h[0][lane][d] = h1;
            h[1][lane][d] = __float2half_rn(r1);
        }
        xpart[dg][lane] = xs;
        __syncthreads();
        if (tid < 32) {
            float tot = 0.f;
            #pragma unroll
            for (int g = 0; g < 8; g++) tot += xpart[g][tid];
            g_xn[n0 + tid] = sqrtf(tot);
            #pragma unroll
            for (int o = 16; o > 0; o >>= 1) tot += __shfl_down_sync(0xffffffffu, tot, o);
            if (tid == 0) atomicAdd(&g_xsum, (double)tot);
        }
        for (int o = tid; o < 32 * 64; o += 256) {
            const int row = o >> 6, s16 = o & 63;
            const int dig = s16 >> 5, dsrc = (s16 & 31) * 8;
            const uint4 v = *(const uint4*)&h[dig][row][dsrc];
            *(uint4*)((char*)g_Aext + (size_t)(n0 + row) * 1024 + s16 * 16) = v;
        }
    }
}

// ---------------- coarse HMMA GEMM (K=256, h1 x g1) -> fp16 scores ----------------
#define SMEM_TOTAL (1024 + 3 * 32768 + 512)

__device__ __forceinline__ void fill_stage(uint32_t sb, const char* Aab, const char* Bgb,
                                           int tid, int g) {
    const int slot = g % 3;
    const uint32_t SA = sb + slot * 32768;
    const uint32_t SB = SA + 16384;
    const char* As = Aab + g * 128;
    const char* Bs = Bgb + g * 128;
    #pragma unroll
    for (int o = 0; o < 4; o++) {
        const int idx = tid + o * 256, row = idx >> 3, c16 = idx & 7;
        const uint32_t sw = (uint32_t)(c16 * 16) ^ (uint32_t)((row & 7) * 16);
        CP_ASYNC16(SA + row * 128 + sw, As + (size_t)row * 1024 + c16 * 16);
        CP_ASYNC16(SB + row * 128 + sw, Bs + (size_t)row * 512  + c16 * 16);
    }
}

__global__ void __launch_bounds__(256, 2) gemm_kernel() {
    extern __shared__ char smem[];
    const uint32_t sbr = smem_u32(smem);
    const uint32_t sb = (sbr + 1023) & ~1023u;
    char* smbase = smem + (sb - sbr);
    float* swn = (float*)(smbase + 3 * 32768);

    const int tid = threadIdx.x, warp = tid >> 5, lane = tid & 31;
    const int warp_m = warp & 3;
    const int warp_n = warp >> 2;
    const int n0 = blockIdx.x * 128;
    const int cbase = blockIdx.y * 128;
    const char* Aab = (const char*)g_Aext + (size_t)n0 * 1024;
    const char* Bgb = (const char*)g_Bg + (size_t)cbase * 512;

    if (tid < 128) swn[tid] = g_wn2[cbase + tid];

    fill_stage(sb, Aab, Bgb, tid, 0); CP_COMMIT();
    fill_stage(sb, Aab, Bgb, tid, 1); CP_COMMIT();

    float c[2][8][4];
    #pragma unroll
    for (int mt = 0; mt < 2; mt++)
        #pragma unroll
        for (int nt = 0; nt < 8; nt++)
            #pragma unroll
            for (int j = 0; j < 4; j++) c[mt][nt][j] = 0.f;

    const int arowL = (lane & 15);
    const uint32_t aLow = (uint32_t)((lane >> 4) << 4);
    const int browL = ((lane >> 4) & 1) * 8 + (lane & 7);
    const uint32_t bKb = (uint32_t)(((lane >> 3) & 1) * 16);
    const uint32_t bswz = (uint32_t)((lane & 7) * 16);

    for (int g = 0; g < 4; g++) {
        CP_WAIT1();
        __syncthreads();
        if (g + 2 < 4) fill_stage(sb, Aab, Bgb, tid, g + 2);
        CP_COMMIT();
        const uint32_t SA = sb + (g % 3) * 32768;
        const uint32_t SB = SA + 16384;
        #pragma unroll
        for (int k16 = 0; k16 < 4; k16++) {
            const uint32_t kOff = (uint32_t)(k16 * 32);
            uint32_t a[2][4];
            #pragma unroll
            for (int mt = 0; mt < 2; mt++) {
                const int arow = warp_m * 32 + mt * 16 + arowL;
                LDMATRIX_X4(a[mt][0], a[mt][1], a[mt][2], a[mt][3],
                            SA + arow * 128 + ((kOff + aLow) ^ (uint32_t)((arow & 7) * 16)));
            }
            #pragma unroll
            for (int np = 0; np < 4; np++) {
                uint32_t b0, b1, b2, b3;
                const uint32_t brow = (uint32_t)(warp_n * 64 + np * 16 + browL);
                LDMATRIX_X4(b0, b1, b2, b3, SB + brow * 128 + ((kOff + bKb) ^ bswz));
                #pragma unroll
                for (int mt = 0; mt < 2; mt++) {
                    MMA16816(c[mt][2 * np][0], c[mt][2 * np][1], c[mt][2 * np][2], c[mt][2 * np][3],
                             a[mt][0], a[mt][1], a[mt][2], a[mt][3], b0, b1);
                    MMA16816(c[mt][2 * np + 1][0], c[mt][2 * np + 1][1],
                             c[mt][2 * np + 1][2], c[mt][2 * np + 1][3],
                             a[mt][0], a[mt][1], a[mt][2], a[mt][3], b2, b3);
                }
            }
        }
    }

    // epilogue: score = 2*dot - wn2, smem repack, coalesced 16B stores
    __syncthreads();
    uint32_t* sp = (uint32_t*)smbase;
    #pragma unroll
    for (int mt = 0; mt < 2; mt++) {
        const int r0 = warp_m * 32 + mt * 16 + (lane >> 2);
        #pragma unroll
        for (int nt = 0; nt < 8; nt++) {
            const int pp = warp_n * 32 + nt * 4 + (lane & 3);
            const int cc = warp_n * 64 + nt * 8 + (lane & 3) * 2;
            const float w0 = swn[cc], w1 = swn[cc + 1];
            __half2 lo = __floats2half2_rn(2.f * c[mt][nt][0] - w0, 2.f * c[mt][nt][1] - w1);
            __half2 hi = __floats2half2_rn(2.f * c[mt][nt][2] - w0, 2.f * c[mt][nt][3] - w1);
            sp[r0 * 66 + pp]       = *(uint32_t*)&lo;
            sp[(r0 + 8) * 66 + pp] = *(uint32_t*)&hi;
        }
    }
    __syncthreads();
    #pragma unroll
    for (int it = 0; it < 8; it++) {
        const int idx = tid + it * 256;
        const int row = idx >> 4, c16 = idx & 15;
        const uint32_t b0 = row * 66 + c16 * 4;
        uint4 v = make_uint4(sp[b0], sp[b0 + 1], sp[b0 + 2], sp[b0 + 3]);
        *(uint4*)((char*)g_scores + (size_t)(n0 + row) * 2048 + cbase * 2 + c16 * 16) = v;
    }
}

// ---------------- fused tail: scan + exact refine + enc rows + out gather ----------------
// block = 32 tokens, 1024 threads (warp per token)
__global__ void __launch_bounds__(1024) tail_kernel(const float* __restrict__ weight,
                                                    float* __restrict__ enc,
                                                    float* __restrict__ out) {
    const int tid = threadIdx.x, lane = tid & 31, warp = tid >> 5;
    const int t0 = blockIdx.x * 32;
    const int t = t0 + warp;
    __shared__ int six[32];
    __shared__ double bsh[32];
    __shared__ float q[32][257];

    // ---- phase 1: per-warp scan of 1024 coarse scores ----
    const uint4* srow = (const uint4*)((const char*)g_scores + (size_t)t * 2048);
    float sc[4][8];
    #pragma unroll
    for (int i = 0; i < 4; i++) {
        uint4 v = srow[i * 32 + lane];
        uint32_t u[4] = {v.x, v.y, v.z, v.w};
        #pragma unroll
        for (int qq = 0; qq < 4; qq++) {
            float2 f = __half22float2(*(const __half2*)&u[qq]);
            sc[i][qq * 2] = f.x; sc[i][qq * 2 + 1] = f.y;
        }
    }
    float M = -3.4e38f;
    #pragma unroll
    for (int i = 0; i < 4; i++)
        #pragma unroll
        for (int j = 0; j < 8; j++) M = fmaxf(M, sc[i][j]);
    #pragma unroll
    for (int x = 16; x > 0; x >>= 1) M = fmaxf(M, __shfl_xor_sync(0xffffffffu, M, x));

    const float gmaxn = sqrtf(__int_as_float(g_gn2max));
    const float T = g_xn[t] * gmaxn * (1.f / 256.f) + 0.004f * fabsf(M) + 0.25f;
    const float thresh = M - T;

    // reconstruct x from digits (err ~2^-22)
    float xr[8];
    {
        const __half* xa = g_Aext + (size_t)t * 512 + lane * 8;
        uint4 v1 = *(const uint4*)xa;
        uint4 v2 = *(const uint4*)(xa + 256);
        const uint32_t* u1 = (const uint32_t*)&v1;
        const uint32_t* u2 = (const uint32_t*)&v2;
        #pragma unroll
        for (int qq = 0; qq < 4; qq++) {
            float2 a = __half22float2(*(const __half2*)&u1[qq]);
            float2 b = __half22float2(*(const __half2*)&u2[qq]);
            xr[qq * 2]     = a.x + b.x;
            xr[qq * 2 + 1] = a.y + b.y;
        }
    }

    float bestE = -3.4e38f; int bidx = 0x7FFFFFFF;
    #pragma unroll 1
    for (int i = 0; i < 4; i++) {
        #pragma unroll 1
        for (int j = 0; j < 8; j++) {
            uint32_t bal = __ballot_sync(0xffffffffu, sc[i][j] >= thresh);
            while (bal) {
                const int src = __ffs(bal) - 1;
                bal &= bal - 1;
                const int code = i * 256 + src * 8 + j;
                const float* w = weight + (size_t)code * Ddim + lane * 8;
                float d = 0.f;
                #pragma unroll
                for (int qq = 0; qq < 8; qq++) d = fmaf(xr[qq], w[qq], d);
                #pragma unroll
                for (int x = 16; x > 0; x >>= 1) d += __shfl_xor_sync(0xffffffffu, d, x);
                const float s = 2.f * d - g_wn2[code];
                if (s > bestE || (s == bestE && code < bidx)) { bestE = s; bidx = code; }
            }
        }
    }
    if (lane == 0) {
        six[warp] = bidx;
        bsh[warp] = (double)bestE;
        atomicAdd(&g_counts[bidx], 1);
    }

    // ---- enc row for this token: zero + one-hot ----
    {
        const float2 z = make_float2(0.f, 0.f);
        float2* row = (float2*)(enc + (size_t)t * Kcode);
        #pragma unroll
        for (int i = 0; i < 16; i++) row[lane + i * 32] = z;
        __syncwarp();
        if (lane == 0) enc[(size_t)t * Kcode + bidx] = 1.0f;
    }

    __syncthreads();
    if (tid == 0) {
        double s = 0.0;
        #pragma unroll
        for (int w8 = 0; w8 < 32; w8++) s += bsh[w8];
        atomicAdd(&g_bsum, s);
    }

    // ---- phase 2: gather codebook rows -> out (BCHW) ----
    for (int e4 = tid; e4 < 32 * 64; e4 += 1024) {
        const int tt = e4 >> 6, d4 = (e4 & 63) * 4;
        float4 v = *(const float4*)&weight[(size_t)six[tt] * Ddim + d4];
        q[tt][d4] = v.x; q[tt][d4 + 1] = v.y; q[tt][d4 + 2] = v.z; q[tt][d4 + 3] = v.w;
    }
    __syncthreads();
    const int b = t0 / HW, hw0 = t0 % HW;
    float* ob = out + (size_t)b * Ddim * HW;
    #pragma unroll 4
    for (int ch = warp; ch < Ddim; ch += 32)
        ob[(size_t)ch * HW + hw0 + lane] = q[lane][ch];
}

__global__ void finalize_kernel(float* __restrict__ outLoss, float* __restrict__ outEnt) {
    __shared__ double sh[256];
    const int tid = threadIdx.x;
    double s = 0.0;
    for (int k = tid; k < Kcode; k += 256) {
        const float p = (float)g_counts[k] * (1.0f / (float)Ntok);
        s += (double)(p * logf(p + 1e-10f));
    }
    sh[tid] = s; __syncthreads();
    for (int o = 128; o > 0; o >>= 1) { if (tid < o) sh[tid] += sh[tid + o]; __syncthreads(); }
    if (tid == 0) {
        outEnt[0]  = (float)(-sh[0]);
        outLoss[0] = (float)(0.25 * (g_xsum - g_bsum) / (double)((size_t)Ntok * Ddim));
    }
}

// ---------------- launch ----------------
extern "C" void kernel_launch(void* const* d_in, const int* in_sizes, int n_in,
                              void* d_out, int out_size) {
    const float* input  = (const float*)d_in[0];
    const float* weight = (const float*)d_in[1];
    float* out     = (float*)d_out;
    float* outLoss = out + OUT_ELEMS;
    float* outEnt  = outLoss + 1;
    float* enc     = outEnt + 1;

    static int attr_done = 0;
    if (!attr_done) {
        cudaFuncSetAttribute(gemm_kernel, cudaFuncAttributeMaxDynamicSharedMemorySize, SMEM_TOTAL);
        attr_done = 1;
    }

    zero_kernel<<<1, 1024>>>();
    conv_kernel<<<2048, 256>>>(weight, input);
    gemm_kernel<<<dim3(256, 8), 256, SMEM_TOTAL>>>();
    tail_kernel<<<Ntok / 32, 1024>>>(weight, enc, out);
    finalize_kernel<<<1, 256>>>(outLoss, outEnt);
}

// round 11
// speedup vs baseline: 2.6718x; 1.1656x over previous
#include <cuda_runtime.h>
#include <cuda_fp16.h>
#include <cstdint>

#define HW    1024
#define Ntok  32768
#define Kcode 1024
#define Ddim  256
#define OUT_ELEMS ((size_t)8388608)
#define CAP   64

// static scratch
__device__ __align__(128) __half g_Aext[(size_t)Ntok * 512];   // 32 MB [h1|h2]
__device__ __align__(128) __half g_Bg[Kcode * 256];            // g1 digits
__device__ __align__(128) unsigned short g_cand[(size_t)Ntok * CAP];  // 4 MB
__device__ unsigned int g_bmax[Ntok];     // running coarse max (ordered bits)
__device__ int    g_ccnt[Ntok];
__device__ float  g_wn2[Kcode];
__device__ float  g_xn[Ntok];
__device__ int    g_gn2max;
__device__ int    g_counts[Kcode];
__device__ double g_xsum, g_bsum;

// ---------------- PTX helpers ----------------
__device__ __forceinline__ uint32_t smem_u32(const void* p) {
    uint32_t a;
    asm("{ .reg .u64 t; cvta.to.shared.u64 t, %1; cvt.u32.u64 %0, t; }" : "=r"(a) : "l"(p));
    return a;
}
#define CP_ASYNC16(dst, src) \
    asm volatile("cp.async.cg.shared.global [%0], [%1], 16;" :: "r"(dst), "l"(src) : "memory")
#define CP_COMMIT() asm volatile("cp.async.commit_group;" ::: "memory")
#define CP_WAIT1()  asm volatile("cp.async.wait_group 1;" ::: "memory")

#define LDMATRIX_X4(r0, r1, r2, r3, addr) \
    asm volatile("ldmatrix.sync.aligned.m8n8.x4.shared.b16 {%0,%1,%2,%3}, [%4];" \
        : "=r"(r0), "=r"(r1), "=r"(r2), "=r"(r3) : "r"(addr))

#define MMA16816(c0, c1, c2, c3, a0, a1, a2, a3, b0, b1) \
    asm volatile("mma.sync.aligned.m16n8k16.row.col.f32.f16.f16.f32 " \
        "{%0,%1,%2,%3}, {%4,%5,%6,%7}, {%8,%9}, {%0,%1,%2,%3};" \
        : "+f"(c0), "+f"(c1), "+f"(c2), "+f"(c3) \
        : "r"(a0), "r"(a1), "r"(a2), "r"(a3), "r"(b0), "r"(b1))

// ---------------- zero / idempotency ----------------
__global__ void zero_kernel() {
    const int i = blockIdx.x * 1024 + threadIdx.x;   // 32 x 1024
    if (i < Ntok)  { g_bmax[i] = 0u; g_ccnt[i] = 0; }
    if (i < Kcode) g_counts[i] = 0;
    if (i == 0) { g_xsum = 0.0; g_bsum = 0.0; g_gn2max = 0; }
}

// ---------------- merged conv: [0,1024) codes, [1024,2048) token tiles ----------------
__global__ void __launch_bounds__(256) conv_kernel(const float* __restrict__ weight,
                                                   const float* __restrict__ input) {
    const int tid = threadIdx.x;
    if (blockIdx.x < 1024) {
        __shared__ float red[256];
        const int k = blockIdx.x;
        const float x = weight[(size_t)k * Ddim + tid];
        g_Bg[(size_t)k * 256 + tid] = __float2half_rn(x);
        red[tid] = x * x;
        __syncthreads();
        for (int o = 128; o > 0; o >>= 1) {
            if (tid < o) red[tid] += red[tid + o];
            __syncthreads();
        }
        if (tid == 0) {
            g_wn2[k] = red[0];
            atomicMax(&g_gn2max, __float_as_int(red[0]));
        }
    } else {
        __shared__ __half h[2][32][264];
        __shared__ float xpart[8][33];
        const int lane = tid & 31, dg = tid >> 5;
        const int n0 = (blockIdx.x - 1024) * 32;
        const int b = n0 / HW, hw0 = n0 % HW;
        const float* ib = input + (size_t)b * Ddim * HW + hw0;
        float xs = 0.f;
        for (int d = dg; d < Ddim; d += 8) {
            float x = ib[(size_t)d * HW + lane];
            xs += x * x;
            __half h1 = __float2half_rn(x);
            float r1 = x - __half2float(h1);
            h[0][lane][d] = h1;
            h[1][lane][d] = __float2half_rn(r1);
        }
        xpart[dg][lane] = xs;
        __syncthreads();
        if (tid < 32) {
            float tot = 0.f;
            #pragma unroll
            for (int g = 0; g < 8; g++) tot += xpart[g][tid];
            g_xn[n0 + tid] = sqrtf(tot);
            #pragma unroll
            for (int o = 16; o > 0; o >>= 1) tot += __shfl_down_sync(0xffffffffu, tot, o);
            if (tid == 0) atomicAdd(&g_xsum, (double)tot);
        }
        for (int o = tid; o < 32 * 64; o += 256) {
            const int row = o >> 6, s16 = o & 63;
            const int dig = s16 >> 5, dsrc = (s16 & 31) * 8;
            const uint4 v = *(const uint4*)&h[dig][row][dsrc];
            *(uint4*)((char*)g_Aext + (size_t)(n0 + row) * 1024 + s16 * 16) = v;
        }
    }
}

// ---------------- coarse HMMA GEMM + candidate push + enc zeroing ----------------
#define SMEM_TOTAL (1024 + 3 * 32768 + 512)

__device__ __forceinline__ void fill_stage(uint32_t sb, const char* Aab, const char* Bgb,
                                           int tid, int g) {
    const int slot = g % 3;
    const uint32_t SA = sb + slot * 32768;
    const uint32_t SB = SA + 16384;
    const char* As = Aab + g * 128;
    const char* Bs = Bgb + g * 128;
    #pragma unroll
    for (int o = 0; o < 4; o++) {
        const int idx = tid + o * 256, row = idx >> 3, c16 = idx & 7;
        const uint32_t sw = (uint32_t)(c16 * 16) ^ (uint32_t)((row & 7) * 16);
        CP_ASYNC16(SA + row * 128 + sw, As + (size_t)row * 1024 + c16 * 16);
        CP_ASYNC16(SB + row * 128 + sw, Bs + (size_t)row * 512  + c16 * 16);
    }
}

__global__ void __launch_bounds__(256, 2) gemm_kernel(float2* __restrict__ enc2) {
    extern __shared__ char smem[];
    const uint32_t sbr = smem_u32(smem);
    const uint32_t sb = (sbr + 1023) & ~1023u;
    char* smbase = smem + (sb - sbr);
    float* swn = (float*)(smbase + 3 * 32768);

    const int tid = threadIdx.x, warp = tid >> 5, lane = tid & 31;
    const int warp_m = warp & 3;
    const int warp_n = warp >> 2;
    const int n0 = blockIdx.x * 128;
    const int cbase = blockIdx.y * 128;
    const char* Aab = (const char*)g_Aext + (size_t)n0 * 1024;
    const char* Bgb = (const char*)g_Bg + (size_t)cbase * 512;

    if (tid < 128) swn[tid] = g_wn2[cbase + tid];

    fill_stage(sb, Aab, Bgb, tid, 0); CP_COMMIT();
    fill_stage(sb, Aab, Bgb, tid, 1); CP_COMMIT();

    float c[2][8][4];
    #pragma unroll
    for (int mt = 0; mt < 2; mt++)
        #pragma unroll
        for (int nt = 0; nt < 8; nt++)
            #pragma unroll
            for (int j = 0; j < 4; j++) c[mt][nt][j] = 0.f;

    const int arowL = (lane & 15);
    const uint32_t aLow = (uint32_t)((lane >> 4) << 4);
    const int browL = ((lane >> 4) & 1) * 8 + (lane & 7);
    const uint32_t bKb = (uint32_t)(((lane >> 3) & 1) * 16);
    const uint32_t bswz = (uint32_t)((lane & 7) * 16);

    // enc zero region for this CTA: 8192 float2 (64 KB)
    const size_t ezBase = (size_t)(blockIdx.y * 256 + blockIdx.x) * 8192;
    const float2 zz = make_float2(0.f, 0.f);

    for (int g = 0; g < 4; g++) {
        CP_WAIT1();
        __syncthreads();
        if (g + 2 < 4) fill_stage(sb, Aab, Bgb, tid, g + 2);
        CP_COMMIT();
        // background enc zeroing (independent stores; hidden under MMA)
        {
            const size_t zb = ezBase + (size_t)g * 2048;
            #pragma unroll
            for (int i = 0; i < 8; i++) enc2[zb + i * 256 + tid] = zz;
        }
        const uint32_t SA = sb + (g % 3) * 32768;
        const uint32_t SB = SA + 16384;
        #pragma unroll
        for (int k16 = 0; k16 < 4; k16++) {
            const uint32_t kOff = (uint32_t)(k16 * 32);
            uint32_t a[2][4];
            #pragma unroll
            for (int mt = 0; mt < 2; mt++) {
                const int arow = warp_m * 32 + mt * 16 + arowL;
                LDMATRIX_X4(a[mt][0], a[mt][1], a[mt][2], a[mt][3],
                            SA + arow * 128 + ((kOff + aLow) ^ (uint32_t)((arow & 7) * 16)));
            }
            #pragma unroll
            for (int np = 0; np < 4; np++) {
                uint32_t b0, b1, b2, b3;
                const uint32_t brow = (uint32_t)(warp_n * 64 + np * 16 + browL);
                LDMATRIX_X4(b0, b1, b2, b3, SB + brow * 128 + ((kOff + bKb) ^ bswz));
                #pragma unroll
                for (int mt = 0; mt < 2; mt++) {
                    MMA16816(c[mt][2 * np][0], c[mt][2 * np][1], c[mt][2 * np][2], c[mt][2 * np][3],
                             a[mt][0], a[mt][1], a[mt][2], a[mt][3], b0, b1);
                    MMA16816(c[mt][2 * np + 1][0], c[mt][2 * np + 1][1],
                             c[mt][2 * np + 1][2], c[mt][2 * np + 1][3],
                             a[mt][0], a[mt][1], a[mt][2], a[mt][3], b2, b3);
                }
            }
        }
    }

    // epilogue: running coarse max + candidate push (no score matrix)
    const float gmaxn = sqrtf(__int_as_float(g_gn2max));
    #pragma unroll
    for (int mt = 0; mt < 2; mt++) {
        #pragma unroll
        for (int grp = 0; grp < 2; grp++) {
            const int row = warp_m * 32 + mt * 16 + grp * 8 + (lane >> 2);
            const int token = n0 + row;
            float sv[16];
            float smax = -3.4e38f;
            #pragma unroll
            for (int nt = 0; nt < 8; nt++) {
                const int cc = warp_n * 64 + nt * 8 + (lane & 3) * 2;
                const float s0 = 2.f * c[mt][nt][2 * grp]     - swn[cc];
                const float s1 = 2.f * c[mt][nt][2 * grp + 1] - swn[cc + 1];
                sv[nt * 2] = s0; sv[nt * 2 + 1] = s1;
                smax = fmaxf(smax, fmaxf(s0, s1));
            }
            smax = fmaxf(smax, __shfl_xor_sync(0xffffffffu, smax, 1));
            smax = fmaxf(smax, __shfl_xor_sync(0xffffffffu, smax, 2));
            const uint32_t f = __float_as_uint(smax);
            const uint32_t ord = (f & 0x80000000u) ? ~f : (f | 0x80000000u);
            uint32_t old = 0;
            if ((lane & 3) == 0) old = atomicMax(&g_bmax[token], ord);
            old = __shfl_sync(0xffffffffu, old, lane & ~3);
            const uint32_t cur = old > ord ? old : ord;
            const float curF = (cur & 0x80000000u) ? __uint_as_float(cur & 0x7FFFFFFFu)
                                                   : __uint_as_float(~cur);
            const float thr = curF - (g_xn[token] * gmaxn * (1.f / 256.f) + 0.25f);
            #pragma unroll
            for (int q = 0; q < 16; q++) {
                if (sv[q] >= thr) {
                    const int code = cbase + warp_n * 64 + (q >> 1) * 8 + (lane & 3) * 2 + (q & 1);
                    const int slot = atomicAdd(&g_ccnt[token], 1);
                    if (slot < CAP) g_cand[(size_t)token * CAP + slot] = (unsigned short)code;
                }
            }
        }
    }
}

// ---------------- fused tail: exact refine from candidates + one-hot + out ----------------
__global__ void __launch_bounds__(1024) tail_kernel(const float* __restrict__ weight,
                                                    float* __restrict__ enc,
                                                    float* __restrict__ out) {
    const int tid = threadIdx.x, lane = tid & 31, warp = tid >> 5;
    const int t0 = blockIdx.x * 32;
    const int t = t0 + warp;
    __shared__ int six[32];
    __shared__ double bsh[32];
    __shared__ float q[32][257];

    // reconstruct x from digits (err ~2^-22)
    float xr[8];
    {
        const __half* xa = g_Aext + (size_t)t * 512 + lane * 8;
        uint4 v1 = *(const uint4*)xa;
        uint4 v2 = *(const uint4*)(xa + 256);
        const uint32_t* u1 = (const uint32_t*)&v1;
        const uint32_t* u2 = (const uint32_t*)&v2;
        #pragma unroll
        for (int qq = 0; qq < 4; qq++) {
            float2 a = __half22float2(*(const __half2*)&u1[qq]);
            float2 b = __half22float2(*(const __half2*)&u2[qq]);
            xr[qq * 2]     = a.x + b.x;
            xr[qq * 2 + 1] = a.y + b.y;
        }
    }

    const int cnt = g_ccnt[t];
    float bestE = -3.4e38f; int bidx = 0x7FFFFFFF;

    if (cnt <= CAP) {
        for (int i = 0; i < cnt; i++) {
            const int code = g_cand[(size_t)t * CAP + i];
            const float4* w4 = (const float4*)(weight + (size_t)code * Ddim) + lane * 2;
            const float4 a = w4[0], b = w4[1];
            float d = xr[0] * a.x;
            d = fmaf(xr[1], a.y, d); d = fmaf(xr[2], a.z, d); d = fmaf(xr[3], a.w, d);
            d = fmaf(xr[4], b.x, d); d = fmaf(xr[5], b.y, d);
            d = fmaf(xr[6], b.z, d); d = fmaf(xr[7], b.w, d);
            #pragma unroll
            for (int x = 16; x > 0; x >>= 1) d += __shfl_xor_sync(0xffffffffu, d, x);
            const float s = 2.f * d - g_wn2[code];
            if (s > bestE || (s == bestE && code < bidx)) { bestE = s; bidx = code; }
        }
    } else {
        // overflow fallback: exact scan over all codes (correct, ~never taken)
        for (int code = 0; code < Kcode; code++) {
            const float4* w4 = (const float4*)(weight + (size_t)code * Ddim) + lane * 2;
            const float4 a = w4[0], b = w4[1];
            float d = xr[0] * a.x;
            d = fmaf(xr[1], a.y, d); d = fmaf(xr[2], a.z, d); d = fmaf(xr[3], a.w, d);
            d = fmaf(xr[4], b.x, d); d = fmaf(xr[5], b.y, d);
            d = fmaf(xr[6], b.z, d); d = fmaf(xr[7], b.w, d);
            #pragma unroll
            for (int x = 16; x > 0; x >>= 1) d += __shfl_xor_sync(0xffffffffu, d, x);
            const float s = 2.f * d - g_wn2[code];
            if (s > bestE || (s == bestE && code < bidx)) { bestE = s; bidx = code; }
        }
    }

    if (lane == 0) {
        six[warp] = bidx;
        bsh[warp] = (double)bestE;
        atomicAdd(&g_counts[bidx], 1);
        enc[(size_t)t * Kcode + bidx] = 1.0f;   // rows pre-zeroed by gemm_kernel
    }

    __syncthreads();
    if (tid == 0) {
        double s = 0.0;
        #pragma unroll
        for (int w8 = 0; w8 < 32; w8++) s += bsh[w8];
        atomicAdd(&g_bsum, s);
    }

    // gather codebook rows -> out (BCHW)
    for (int e4 = tid; e4 < 32 * 64; e4 += 1024) {
        const int tt = e4 >> 6, d4 = (e4 & 63) * 4;
        float4 v = *(const float4*)&weight[(size_t)six[tt] * Ddim + d4];
        q[tt][d4] = v.x; q[tt][d4 + 1] = v.y; q[tt][d4 + 2] = v.z; q[tt][d4 + 3] = v.w;
    }
    __syncthreads();
    const int b = t0 / HW, hw0 = t0 % HW;
    float* ob = out + (size_t)b * Ddim * HW;
    #pragma unroll 4
    for (int ch = warp; ch < Ddim; ch += 32)
        ob[(size_t)ch * HW + hw0 + lane] = q[lane][ch];
}

__global__ void finalize_kernel(float* __restrict__ outLoss, float* __restrict__ outEnt) {
    __shared__ double sh[256];
    const int tid = threadIdx.x;
    double s = 0.0;
    for (int k = tid; k < Kcode; k += 256) {
        const float p = (float)g_counts[k] * (1.0f / (float)Ntok);
        s += (double)(p * logf(p + 1e-10f));
    }
    sh[tid] = s; __syncthreads();
    for (int o = 128; o > 0; o >>= 1) { if (tid < o) sh[tid] += sh[tid + o]; __syncthreads(); }
    if (tid == 0) {
        outEnt[0]  = (float)(-sh[0]);
        outLoss[0] = (float)(0.25 * (g_xsum - g_bsum) / (double)((size_t)Ntok * Ddim));
    }
}

// ---------------- launch ----------------
extern "C" void kernel_launch(void* const* d_in, const int* in_sizes, int n_in,
                              void* d_out, int out_size) {
    const float* input  = (const float*)d_in[0];
    const float* weight = (const float*)d_in[1];
    float* out     = (float*)d_out;
    float* outLoss = out + OUT_ELEMS;
    float* outEnt  = outLoss + 1;
    float* enc     = outEnt + 1;

    static int attr_done = 0;
    if (!attr_done) {
        cudaFuncSetAttribute(gemm_kernel, cudaFuncAttributeMaxDynamicSharedMemorySize, SMEM_TOTAL);
        attr_done = 1;
    }

    zero_kernel<<<32, 1024>>>();
    conv_kernel<<<2048, 256>>>(weight, input);
    gemm_kernel<<<dim3(256, 8), 256, SMEM_TOTAL>>>((float2*)enc);
    tail_kernel<<<Ntok / 32, 1024>>>(weight, enc, out);
    finalize_kernel<<<1, 256>>>(outLoss, outEnt);
}